// round 7
// baseline (speedup 1.0000x reference)
#include <cuda_runtime.h>
#include <cuda_fp16.h>
#include <cstdint>

#define B_    16
#define L_    256
#define D_    512
#define MELS_ 80
#define T_    3072
#define M_ENC (B_ * L_)   // 4096
#define MT_ST 4160        // melT row stride (tokens 0..4095 + constant col 4096)

// Scratch (__device__ globals; no allocation allowed)
__device__ __half g_x    [M_ENC * D_];   // fp16(emb[src]+pos)
__device__ __half g_enc  [M_ENC * D_];   // fp16(relu(enc))
__device__ __half g_dect [M_ENC * D_];   // fp16(relu(dec)) per TOKEN
__device__ int    g_csum [B_ * L_];      // per-batch inclusive duration cumsum
__device__ float  g_melT [MELS_ * MT_ST];// melT[n][token]; col M_ENC = constant
__device__ __half g_wencT[D_ * D_];      // fp16 W^T  [N][K]
__device__ __half g_wdecT[D_ * D_];
__device__ __half g_wgenT[MELS_ * D_];

// ---------------------------------------------------------------------------
__device__ __forceinline__ uint32_t smem_u32(const void* p) {
    return (uint32_t)__cvta_generic_to_shared(p);
}
__device__ __forceinline__ void cpa16(uint32_t dst, const void* src, int srcsize) {
    asm volatile("cp.async.cg.shared.global [%0], [%1], 16, %2;"
                 :: "r"(dst), "l"(src), "r"(srcsize));
}
__device__ __forceinline__ uint32_t sw(uint32_t o) { return o ^ ((o >> 3) & 0x70); }

__device__ __forceinline__ void ldm4(uint32_t* r, uint32_t addr) {
    asm volatile("ldmatrix.sync.aligned.m8n8.x4.shared.b16 {%0,%1,%2,%3}, [%4];"
                 : "=r"(r[0]), "=r"(r[1]), "=r"(r[2]), "=r"(r[3]) : "r"(addr));
}
__device__ __forceinline__ void ldm2(uint32_t* r, uint32_t addr) {
    asm volatile("ldmatrix.sync.aligned.m8n8.x2.shared.b16 {%0,%1}, [%2];"
                 : "=r"(r[0]), "=r"(r[1]) : "r"(addr));
}
__device__ __forceinline__ void mma_f16(float* d, const uint32_t* a, const uint32_t* b) {
    asm volatile(
        "mma.sync.aligned.m16n8k16.row.col.f32.f16.f16.f32 "
        "{%0,%1,%2,%3},{%4,%5,%6,%7},{%8,%9},{%0,%1,%2,%3};"
        : "+f"(d[0]), "+f"(d[1]), "+f"(d[2]), "+f"(d[3])
        : "r"(a[0]), "r"(a[1]), "r"(a[2]), "r"(a[3]), "r"(b[0]), "r"(b[1]));
}

// ---------------------------------------------------------------------------
// prep_all: one kernel, blockIdx.x ranges dispatch independent prep work
//   [0, 2048)        prep_x
//   [2048, 2560)     transpose W_enc / W_dec -> fp16 [N][K]
//   [2560, 2608)     transpose W_gen -> fp16 [N][K]
//   [2608, 2624)     per-batch duration scan -> g_csum
//   [2624]           cmel constant column
// ---------------------------------------------------------------------------
#define NB_PREPX 2048
#define NB_T2    512
#define NB_TG    48
#define NB_SCAN  16
#define NB_ALL   (NB_PREPX + NB_T2 + NB_TG + NB_SCAN + 1)

__global__ void __launch_bounds__(256) prep_all(
    const int* __restrict__ src, const int* __restrict__ dur,
    const float* __restrict__ emb, const float* __restrict__ pos,
    const float* __restrict__ W_enc, const float* __restrict__ W_dec,
    const float* __restrict__ W_gen, const float* __restrict__ b_dec,
    const float* __restrict__ b_gen)
{
    __shared__ float sbuf[32 * 33];      // transpose tile / scan / cmel scratch
    const int bid = blockIdx.x;
    const int tid = threadIdx.x;

    if (bid < NB_PREPX) {
        // prep_x: g_x[m][d] = fp16(emb[src[m]][d] + pos[m % L][d])
        const long idx = (long)bid * 256 + tid;   // float4 index
        const int  m   = (int)(idx >> 7);
        const int  d4  = (int)(idx & 127) * 4;
        float4 e = *(const float4*)(emb + (long)src[m] * D_ + d4);
        float4 p = *(const float4*)(pos + (long)(m & (L_ - 1)) * D_ + d4);
        __half2 h0 = __floats2half2_rn(e.x + p.x, e.y + p.y);
        __half2 h1 = __floats2half2_rn(e.z + p.z, e.w + p.w);
        uint2 u = make_uint2(*(uint32_t*)&h0, *(uint32_t*)&h1);
        *(uint2*)(g_x + idx * 4) = u;
    } else if (bid < NB_PREPX + NB_T2) {
        // 512x512 weight transpose (2 weights x 16 x 16 tiles)
        const int id  = bid - NB_PREPX;
        const int z   = id >> 8;
        const int rem = id & 255;
        const int c0  = (rem & 15) * 32, r0 = (rem >> 4) * 32;
        const float* srcw = z ? W_dec : W_enc;
        __half* dst = z ? g_wdecT : g_wencT;
        const int tx = tid & 31, ty = tid >> 5;
        float (*tile)[33] = (float(*)[33])sbuf;
#pragma unroll
        for (int i = 0; i < 4; i++)
            tile[ty + i * 8][tx] = srcw[(r0 + ty + i * 8) * D_ + c0 + tx];
        __syncthreads();
#pragma unroll
        for (int i = 0; i < 4; i++)
            dst[(long)(c0 + ty + i * 8) * D_ + r0 + tx] =
                __float2half_rn(tile[tx][ty + i * 8]);
    } else if (bid < NB_PREPX + NB_T2 + NB_TG) {
        // W_gen [D][MELS] -> g_wgenT [MELS][D]
        const int id = bid - NB_PREPX - NB_T2;
        const int c0 = (id % 3) * 32, r0 = (id / 3) * 32;
        const int tx = tid & 31, ty = tid >> 5;
        float (*tile)[33] = (float(*)[33])sbuf;
#pragma unroll
        for (int i = 0; i < 4; i++) {
            int r = r0 + ty + i * 8, c = c0 + tx;
            if (c < MELS_) tile[ty + i * 8][tx] = W_gen[r * MELS_ + c];
        }
        __syncthreads();
#pragma unroll
        for (int i = 0; i < 4; i++) {
            int c = c0 + ty + i * 8, r = r0 + tx;
            if (c < MELS_)
                g_wgenT[(long)c * D_ + r] = __float2half_rn(tile[tx][ty + i * 8]);
        }
    } else if (bid < NB_PREPX + NB_T2 + NB_TG + NB_SCAN) {
        // per-batch inclusive scan of durations
        const int b = bid - NB_PREPX - NB_T2 - NB_TG;
        int* csum = (int*)sbuf;
        csum[tid] = dur[b * L_ + tid];
        __syncthreads();
        for (int off = 1; off < L_; off <<= 1) {
            int x = (tid >= off) ? csum[tid - off] : 0;
            __syncthreads();
            csum[tid] += x;
            __syncthreads();
        }
        g_csum[b * L_ + tid] = csum[tid];
    } else {
        // cmel: melT[n][M_ENC] = relu(b_dec) . W_gen[:, n] + b_gen[n]  (fp32)
        float* rd = sbuf;
        for (int k = tid; k < D_; k += 256) {
            float v = b_dec[k]; rd[k] = v > 0.f ? v : 0.f;
        }
        __syncthreads();
        if (tid < MELS_) {
            float s = b_gen[tid];
            for (int k = 0; k < D_; k++) s += rd[k] * W_gen[k * MELS_ + tid];
            g_melT[tid * MT_ST + M_ENC] = s;
        }
    }
}

// ---------------------------------------------------------------------------
// hgemm512: out = fp16(relu(A @ Bt^T + bias)),  M = 4096, K = N = 512, fp16 in
// ---------------------------------------------------------------------------
#define H_ATILE 16384          // 128 rows * 128 B
#define H_STAGE (2 * H_ATILE)  // A + B
#define SMEM512 (2 * H_STAGE + 1024)

__global__ void __launch_bounds__(256, 2) hgemm512(
    const __half* __restrict__ A, const __half* __restrict__ Bt,
    const float* __restrict__ bias, __half* __restrict__ out)
{
    extern __shared__ char dsm[];
    const int tid  = threadIdx.x;
    const int warp = tid >> 5, lane = tid & 31;
    const int m0   = blockIdx.y * 128, n0 = blockIdx.x * 128;

    const uint32_t base = (smem_u32(dsm) + 1023) & ~1023u;
    const uint32_t Aoff[2] = { base, base + H_STAGE };
    const uint32_t Boff[2] = { base + H_ATILE, base + H_STAGE + H_ATILE };

    const int r0  = tid >> 3;
    const int seg = (tid & 7) * 16;
    const char* ap[4];
    const char* bp[4];
    uint32_t dst[4];
#pragma unroll
    for (int i = 0; i < 4; i++) {
        const int r = r0 + i * 32;
        ap[i]  = (const char*)A  + (long)(m0 + r) * D_ * 2;
        bp[i]  = (const char*)Bt + (long)(n0 + r) * D_ * 2;
        dst[i] = sw((uint32_t)(r * 128 + seg));
    }

#define HISSUE(c, s) do {                                                     \
        const int kb = (c) * 128;                                             \
        _Pragma("unroll")                                                     \
        for (int i = 0; i < 4; i++) cpa16(Aoff[s] + dst[i], ap[i] + kb + seg, 16); \
        _Pragma("unroll")                                                     \
        for (int i = 0; i < 4; i++) cpa16(Boff[s] + dst[i], bp[i] + kb + seg, 16); \
        asm volatile("cp.async.commit_group;");                               \
    } while (0)

    const int mbase = (warp & 1) * 64;
    const int nbase = (warp >> 1) * 32;
    const int li  = lane & 7, grp = lane >> 3;
    const int ar  = (grp & 1) * 8 + li,  ak = (grp >> 1) * 16;
    const int br  = (grp >> 1) * 8 + li, bk = (grp & 1) * 16;
    const int g = lane >> 2, t = lane & 3;

    float acc[4][4][4] = {};

    HISSUE(0, 0);
#pragma unroll 1
    for (int c = 0; c < 8; c++) {
        if (c < 7) {
            HISSUE(c + 1, (c + 1) & 1);
            asm volatile("cp.async.wait_group 1;");
        } else {
            asm volatile("cp.async.wait_group 0;");
        }
        __syncthreads();
        const uint32_t Ab = Aoff[c & 1], Bb = Boff[c & 1];
#pragma unroll
        for (int kk = 0; kk < 4; kk++) {
            const int kb2 = kk * 32;
            uint32_t a[4][4], b[4][2];
#pragma unroll
            for (int mf = 0; mf < 4; mf++) {
                uint32_t o = (uint32_t)((mbase + mf * 16 + ar) * 128 + kb2 + ak);
                ldm4(a[mf], Ab + sw(o));
            }
#pragma unroll
            for (int nfp = 0; nfp < 2; nfp++) {
                uint32_t o = (uint32_t)((nbase + nfp * 16 + br) * 128 + kb2 + bk);
                uint32_t r[4]; ldm4(r, Bb + sw(o));
                b[nfp * 2][0] = r[0]; b[nfp * 2][1] = r[1];
                b[nfp * 2 + 1][0] = r[2]; b[nfp * 2 + 1][1] = r[3];
            }
#pragma unroll
            for (int mf = 0; mf < 4; mf++)
#pragma unroll
                for (int nf = 0; nf < 4; nf++)
                    mma_f16(acc[mf][nf], a[mf], b[nf]);
        }
        __syncthreads();
    }

#pragma unroll
    for (int mf = 0; mf < 4; mf++) {
        const long r0g = m0 + mbase + mf * 16 + g;
#pragma unroll
        for (int nf = 0; nf < 4; nf++) {
            const int c = n0 + nbase + nf * 8 + t * 2;
            const float b0 = bias[c], b1 = bias[c + 1];
            float v0 = acc[mf][nf][0] + b0, v1 = acc[mf][nf][1] + b1;
            float v2 = acc[mf][nf][2] + b0, v3 = acc[mf][nf][3] + b1;
            __half2 h0 = __floats2half2_rn(v0 > 0.f ? v0 : 0.f, v1 > 0.f ? v1 : 0.f);
            __half2 h1 = __floats2half2_rn(v2 > 0.f ? v2 : 0.f, v3 > 0.f ? v3 : 0.f);
            *(__half2*)(out + r0g * D_ + c)       = h0;
            *(__half2*)(out + (r0g + 8) * D_ + c) = h1;
        }
    }
#undef HISSUE
}

// ---------------------------------------------------------------------------
// genT: melT[n][token] = dec_tok @ W_gen^T + b_gen
//   64-row M tile (64 CTAs), 8 warps = 4m x 2n, N = 80
// ---------------------------------------------------------------------------
#define GA_TILE 8192           // 64 rows * 128 B
#define HG_BTILE 10240         // 80 rows * 128 B
#define HG_STAGE (GA_TILE + HG_BTILE)
#define SMEM80 (2 * HG_STAGE + 1024)

__global__ void __launch_bounds__(256, 2) genT_kernel(const float* __restrict__ bias)
{
    extern __shared__ char dsm[];
    const int tid  = threadIdx.x;
    const int warp = tid >> 5, lane = tid & 31;
    const int m0   = blockIdx.y * 64;

    const uint32_t base = (smem_u32(dsm) + 1023) & ~1023u;
    const uint32_t Aoff[2] = { base, base + HG_STAGE };
    const uint32_t Boff[2] = { base + GA_TILE, base + HG_STAGE + GA_TILE };

    const int r0  = tid >> 3;
    const int seg = (tid & 7) * 16;
    const char* ap[2]; uint32_t adst[2];
    const char* bp[3]; uint32_t bdst[3]; int bok[3];
#pragma unroll
    for (int i = 0; i < 2; i++) {
        const int r = r0 + i * 32;
        ap[i]   = (const char*)g_dect + (long)(m0 + r) * D_ * 2;
        adst[i] = sw((uint32_t)(r * 128 + seg));
    }
#pragma unroll
    for (int i = 0; i < 3; i++) {
        const int r = r0 + i * 32;
        bok[i]  = (r < MELS_);
        bp[i]   = (const char*)g_wgenT + (long)(bok[i] ? r : 0) * D_ * 2;
        bdst[i] = sw((uint32_t)(r * 128 + seg));
    }

#define GISSUE(c, s) do {                                                     \
        const int kb = (c) * 128;                                             \
        _Pragma("unroll")                                                     \
        for (int i = 0; i < 2; i++) cpa16(Aoff[s] + adst[i], ap[i] + kb + seg, 16); \
        _Pragma("unroll")                                                     \
        for (int i = 0; i < 3; i++)                                           \
            if (bok[i]) cpa16(Boff[s] + bdst[i], bp[i] + kb + seg, 16);       \
        asm volatile("cp.async.commit_group;");                               \
    } while (0)

    const int mbase = (warp & 3) * 16;
    const int nbase = (warp >> 2) * 40;
    const int li  = lane & 7, grp = lane >> 3;
    const int ar  = (grp & 1) * 8 + li,  ak = (grp >> 1) * 16;
    const int br  = (grp >> 1) * 8 + li, bk = (grp & 1) * 16;
    const int g = lane >> 2, t = lane & 3;

    float acc[5][4] = {};

    GISSUE(0, 0);
#pragma unroll 1
    for (int c = 0; c < 8; c++) {
        if (c < 7) {
            GISSUE(c + 1, (c + 1) & 1);
            asm volatile("cp.async.wait_group 1;");
        } else {
            asm volatile("cp.async.wait_group 0;");
        }
        __syncthreads();
        const uint32_t Ab = Aoff[c & 1], Bb = Boff[c & 1];
#pragma unroll
        for (int kk = 0; kk < 4; kk++) {
            const int kb2 = kk * 32;
            uint32_t a[4], b[5][2];
            {
                uint32_t o = (uint32_t)((mbase + ar) * 128 + kb2 + ak);
                ldm4(a, Ab + sw(o));
            }
#pragma unroll
            for (int nfp = 0; nfp < 2; nfp++) {
                uint32_t o = (uint32_t)((nbase + nfp * 16 + br) * 128 + kb2 + bk);
                uint32_t r[4]; ldm4(r, Bb + sw(o));
                b[nfp * 2][0] = r[0]; b[nfp * 2][1] = r[1];
                b[nfp * 2 + 1][0] = r[2]; b[nfp * 2 + 1][1] = r[3];
            }
            {
                uint32_t o = (uint32_t)((nbase + 32 + li) * 128 + kb2 + (grp & 1) * 16);
                ldm2(b[4], Bb + sw(o));
            }
#pragma unroll
            for (int nf = 0; nf < 5; nf++)
                mma_f16(acc[nf], a, b[nf]);
        }
        __syncthreads();
    }

    // transposed epilogue: melT[n][token]
    const int tok = m0 + mbase + g;
#pragma unroll
    for (int nf = 0; nf < 5; nf++) {
        const int n = nbase + nf * 8 + t * 2;
        const float b0 = bias[n], b1 = bias[n + 1];
        float* p0 = g_melT + (long)n * MT_ST;
        float* p1 = p0 + MT_ST;
        p0[tok]     = acc[nf][0] + b0;
        p1[tok]     = acc[nf][1] + b1;
        p0[tok + 8] = acc[nf][2] + b0;
        p1[tok + 8] = acc[nf][3] + b1;
    }
#undef GISSUE
}

// ---------------------------------------------------------------------------
// expand: binary-search tokens + gather melT   mel[b, n, t] = melT[n][tok(b,t)]
// ---------------------------------------------------------------------------
__global__ void __launch_bounds__(256) expand_kernel(float* __restrict__ mel) {
    __shared__ int csum[L_];
    const int b   = blockIdx.y;
    const int t0  = blockIdx.x * 256;
    const int tid = threadIdx.x;

    csum[tid] = g_csum[b * L_ + tid];
    __syncthreads();

    const int t = t0 + tid;
    int lo = 0, hi = L_;
    while (lo < hi) {
        int mid = (lo + hi) >> 1;
        if (csum[mid] > t) hi = mid; else lo = mid + 1;
    }
    const int tok = (lo < L_) ? (b * L_ + lo) : M_ENC;

    float* out = mel + (long)b * MELS_ * T_ + t;
    const float* mt = g_melT + tok;
#pragma unroll 8
    for (int n = 0; n < MELS_; n++)
        out[(long)n * T_] = __ldg(mt + (long)n * MT_ST);
}

// ---------------------------------------------------------------------------
// duration head (reads fp16 enc)
// ---------------------------------------------------------------------------
__global__ void dur_kernel(const float* __restrict__ Wd, const float* __restrict__ bd,
                           float* __restrict__ out)
{
    const int m    = blockIdx.x * 8 + threadIdx.y;
    const int lane = threadIdx.x;
    float s = 0.f;
    for (int k = lane; k < D_; k += 32)
        s += __half2float(g_enc[(long)m * D_ + k]) * Wd[k];
#pragma unroll
    for (int o = 16; o; o >>= 1) s += __shfl_xor_sync(0xffffffffu, s, o);
    if (lane == 0) out[m] = s + bd[0];
}

// ---------------------------------------------------------------------------
extern "C" void kernel_launch(void* const* d_in, const int* in_sizes, int n_in,
                              void* d_out, int out_size)
{
    const int* src = (const int*)d_in[0];
    const int* dur = (const int*)d_in[1];
    int p = 2;
    if (p < n_in && in_sizes[2] <= 4) p = 3;  // skip scalar T if materialized
    const float* emb   = (const float*)d_in[p + 0];
    const float* pos   = (const float*)d_in[p + 1];
    const float* W_enc = (const float*)d_in[p + 2];
    const float* b_enc = (const float*)d_in[p + 3];
    const float* W_dur = (const float*)d_in[p + 4];
    const float* b_dur = (const float*)d_in[p + 5];
    const float* W_dec = (const float*)d_in[p + 6];
    const float* b_dec = (const float*)d_in[p + 7];
    const float* W_gen = (const float*)d_in[p + 8];
    const float* b_gen = (const float*)d_in[p + 9];

    float* mel  = (float*)d_out;                         // [B, MELS, T]
    float* durp = (float*)d_out + (long)B_ * MELS_ * T_; // [B, L]

    static bool attr_done = false;
    if (!attr_done) {
        cudaFuncSetAttribute(hgemm512,    cudaFuncAttributeMaxDynamicSharedMemorySize, SMEM512);
        cudaFuncSetAttribute(genT_kernel, cudaFuncAttributeMaxDynamicSharedMemorySize, SMEM80);
        attr_done = true;
    }

    __half *d_wencT, *d_wdecT, *d_x, *d_enc, *d_dect;
    cudaGetSymbolAddress((void**)&d_wencT, g_wencT);
    cudaGetSymbolAddress((void**)&d_wdecT, g_wdecT);
    cudaGetSymbolAddress((void**)&d_x,     g_x);
    cudaGetSymbolAddress((void**)&d_enc,   g_enc);
    cudaGetSymbolAddress((void**)&d_dect,  g_dect);

    prep_all<<<NB_ALL, 256>>>(src, dur, emb, pos, W_enc, W_dec, W_gen, b_dec, b_gen);
    hgemm512<<<dim3(D_ / 128, M_ENC / 128), 256, SMEM512>>>(d_x, d_wencT, b_enc, d_enc);
    hgemm512<<<dim3(D_ / 128, M_ENC / 128), 256, SMEM512>>>(d_enc, d_wdecT, b_dec, d_dect);
    genT_kernel<<<dim3(1, M_ENC / 64), 256, SMEM80>>>(b_gen);
    expand_kernel<<<dim3(T_ / 256, B_), 256>>>(mel);
    dur_kernel<<<M_ENC / 8, dim3(32, 8)>>>(W_dur, b_dur, durp);
}

// round 8
// speedup vs baseline: 1.3241x; 1.3241x over previous
#include <cuda_runtime.h>
#include <cuda_fp16.h>
#include <cstdint>

#define B_    16
#define L_    256
#define D_    512
#define MELS_ 80
#define T_    3072
#define M_ENC (B_ * L_)   // 4096
#define MT_ST 4160        // melT row stride (tokens 0..4095 + constant col 4096)
#define NCTA  128

// Scratch (__device__ globals; no allocation allowed)
__device__ __half g_x    [M_ENC * D_];
__device__ __half g_enc  [M_ENC * D_];
__device__ __half g_dect [M_ENC * D_];
__device__ int    g_csum [B_ * L_];
__device__ float  g_melT [MELS_ * MT_ST];
__device__ __half g_wencT[D_ * D_];
__device__ __half g_wdecT[D_ * D_];
__device__ __half g_wgenT[MELS_ * D_];
__device__ unsigned g_bar;               // grid barrier counter (reset each run)

// ---------------------------------------------------------------------------
__device__ __forceinline__ uint32_t smem_u32(const void* p) {
    return (uint32_t)__cvta_generic_to_shared(p);
}
__device__ __forceinline__ void cpa16(uint32_t dst, const void* src, int srcsize) {
    asm volatile("cp.async.cg.shared.global [%0], [%1], 16, %2;"
                 :: "r"(dst), "l"(src), "r"(srcsize));
}
__device__ __forceinline__ uint32_t sw(uint32_t o) { return o ^ ((o >> 3) & 0x70); }

__device__ __forceinline__ void ldm4(uint32_t* r, uint32_t addr) {
    asm volatile("ldmatrix.sync.aligned.m8n8.x4.shared.b16 {%0,%1,%2,%3}, [%4];"
                 : "=r"(r[0]), "=r"(r[1]), "=r"(r[2]), "=r"(r[3]) : "r"(addr));
}
__device__ __forceinline__ void ldm2(uint32_t* r, uint32_t addr) {
    asm volatile("ldmatrix.sync.aligned.m8n8.x2.shared.b16 {%0,%1}, [%2];"
                 : "=r"(r[0]), "=r"(r[1]) : "r"(addr));
}
__device__ __forceinline__ void mma_f16(float* d, const uint32_t* a, const uint32_t* b) {
    asm volatile(
        "mma.sync.aligned.m16n8k16.row.col.f32.f16.f16.f32 "
        "{%0,%1,%2,%3},{%4,%5,%6,%7},{%8,%9},{%0,%1,%2,%3};"
        : "+f"(d[0]), "+f"(d[1]), "+f"(d[2]), "+f"(d[3])
        : "r"(a[0]), "r"(a[1]), "r"(a[2]), "r"(a[3]), "r"(b[0]), "r"(b[1]));
}

// grid barrier: all NCTA CTAs arrive; spin until count reaches target
__device__ __forceinline__ void grid_bar(unsigned target) {
    __syncthreads();
    if (threadIdx.x == 0) {
        __threadfence();
        atomicAdd(&g_bar, 1u);
        while (*(volatile unsigned*)&g_bar < target) __nanosleep(64);
        __threadfence();
    }
    __syncthreads();
}

// ---------------------------------------------------------------------------
// P0 prep units
// ---------------------------------------------------------------------------
#define NB_PREPX 2048
#define NB_T2    512
#define NB_TG    48
#define NB_SCAN  16
#define NB_ALL   (NB_PREPX + NB_T2 + NB_TG + NB_SCAN + 1)   // 2625

__device__ void prep_unit(int bid, float* sbuf,
    const int* __restrict__ src, const int* __restrict__ dur,
    const float* __restrict__ emb, const float* __restrict__ pos,
    const float* __restrict__ W_enc, const float* __restrict__ W_dec,
    const float* __restrict__ W_gen, const float* __restrict__ b_dec,
    const float* __restrict__ b_gen)
{
    const int tid = threadIdx.x;
    if (bid < NB_PREPX) {
        const long idx = (long)bid * 256 + tid;
        const int  m   = (int)(idx >> 7);
        const int  d4  = (int)(idx & 127) * 4;
        float4 e = *(const float4*)(emb + (long)src[m] * D_ + d4);
        float4 p = *(const float4*)(pos + (long)(m & (L_ - 1)) * D_ + d4);
        __half2 h0 = __floats2half2_rn(e.x + p.x, e.y + p.y);
        __half2 h1 = __floats2half2_rn(e.z + p.z, e.w + p.w);
        uint2 u = make_uint2(*(uint32_t*)&h0, *(uint32_t*)&h1);
        *(uint2*)(g_x + idx * 4) = u;
    } else if (bid < NB_PREPX + NB_T2) {
        const int id  = bid - NB_PREPX;
        const int z   = id >> 8;
        const int rem = id & 255;
        const int c0  = (rem & 15) * 32, r0 = (rem >> 4) * 32;
        const float* srcw = z ? W_dec : W_enc;
        __half* dst = z ? g_wdecT : g_wencT;
        const int tx = tid & 31, ty = tid >> 5;
        float (*tile)[33] = (float(*)[33])sbuf;
#pragma unroll
        for (int i = 0; i < 4; i++)
            tile[ty + i * 8][tx] = srcw[(r0 + ty + i * 8) * D_ + c0 + tx];
        __syncthreads();
#pragma unroll
        for (int i = 0; i < 4; i++)
            dst[(long)(c0 + ty + i * 8) * D_ + r0 + tx] =
                __float2half_rn(tile[tx][ty + i * 8]);
        __syncthreads();
    } else if (bid < NB_PREPX + NB_T2 + NB_TG) {
        const int id = bid - NB_PREPX - NB_T2;
        const int c0 = (id % 3) * 32, r0 = (id / 3) * 32;
        const int tx = tid & 31, ty = tid >> 5;
        float (*tile)[33] = (float(*)[33])sbuf;
#pragma unroll
        for (int i = 0; i < 4; i++) {
            int r = r0 + ty + i * 8, c = c0 + tx;
            if (c < MELS_) tile[ty + i * 8][tx] = W_gen[r * MELS_ + c];
        }
        __syncthreads();
#pragma unroll
        for (int i = 0; i < 4; i++) {
            int c = c0 + ty + i * 8, r = r0 + tx;
            if (c < MELS_)
                g_wgenT[(long)c * D_ + r] = __float2half_rn(tile[tx][ty + i * 8]);
        }
        __syncthreads();
    } else if (bid < NB_PREPX + NB_T2 + NB_TG + NB_SCAN) {
        const int b = bid - NB_PREPX - NB_T2 - NB_TG;
        int* csum = (int*)sbuf;
        csum[tid] = dur[b * L_ + tid];
        __syncthreads();
        for (int off = 1; off < L_; off <<= 1) {
            int x = (tid >= off) ? csum[tid - off] : 0;
            __syncthreads();
            csum[tid] += x;
            __syncthreads();
        }
        g_csum[b * L_ + tid] = csum[tid];
        __syncthreads();
    } else {
        float* rd = sbuf;
        for (int k = tid; k < D_; k += 256) {
            float v = b_dec[k]; rd[k] = v > 0.f ? v : 0.f;
        }
        __syncthreads();
        if (tid < MELS_) {
            float s = b_gen[tid];
            for (int k = 0; k < D_; k++) s += rd[k] * W_gen[k * MELS_ + tid];
            g_melT[tid * MT_ST + M_ENC] = s;
        }
        __syncthreads();
    }
}

// ---------------------------------------------------------------------------
// hgemm512 tile (device): out = fp16(relu(A @ Bt^T + bias)) for tile (bx, by)
// ---------------------------------------------------------------------------
#define H_ATILE 16384
#define H_STAGE (2 * H_ATILE)
#define SMEM512 (2 * H_STAGE + 1024)     // 66560

__device__ void dev_hgemm512(const __half* __restrict__ A, const __half* __restrict__ Bt,
                             const float* __restrict__ bias, __half* __restrict__ out,
                             int bx, int by, char* dsm)
{
    const int tid  = threadIdx.x;
    const int warp = tid >> 5, lane = tid & 31;
    const int m0   = by * 128, n0 = bx * 128;

    const uint32_t base = (smem_u32(dsm) + 1023) & ~1023u;
    const uint32_t Aoff[2] = { base, base + H_STAGE };
    const uint32_t Boff[2] = { base + H_ATILE, base + H_STAGE + H_ATILE };

    const int r0  = tid >> 3;
    const int seg = (tid & 7) * 16;
    const char* ap[4];
    const char* bp[4];
    uint32_t dst[4];
#pragma unroll
    for (int i = 0; i < 4; i++) {
        const int r = r0 + i * 32;
        ap[i]  = (const char*)A  + (long)(m0 + r) * D_ * 2;
        bp[i]  = (const char*)Bt + (long)(n0 + r) * D_ * 2;
        dst[i] = sw((uint32_t)(r * 128 + seg));
    }

#define HISSUE(c, s) do {                                                     \
        const int kb = (c) * 128;                                             \
        _Pragma("unroll")                                                     \
        for (int i = 0; i < 4; i++) cpa16(Aoff[s] + dst[i], ap[i] + kb + seg, 16); \
        _Pragma("unroll")                                                     \
        for (int i = 0; i < 4; i++) cpa16(Boff[s] + dst[i], bp[i] + kb + seg, 16); \
        asm volatile("cp.async.commit_group;");                               \
    } while (0)

    const int mbase = (warp & 1) * 64;
    const int nbase = (warp >> 1) * 32;
    const int li  = lane & 7, grp = lane >> 3;
    const int ar  = (grp & 1) * 8 + li,  ak = (grp >> 1) * 16;
    const int br  = (grp >> 1) * 8 + li, bk = (grp & 1) * 16;
    const int g = lane >> 2, t = lane & 3;

    float acc[4][4][4] = {};

    HISSUE(0, 0);
#pragma unroll 1
    for (int c = 0; c < 8; c++) {
        if (c < 7) {
            HISSUE(c + 1, (c + 1) & 1);
            asm volatile("cp.async.wait_group 1;");
        } else {
            asm volatile("cp.async.wait_group 0;");
        }
        __syncthreads();
        const uint32_t Ab = Aoff[c & 1], Bb = Boff[c & 1];
#pragma unroll
        for (int kk = 0; kk < 4; kk++) {
            const int kb2 = kk * 32;
            uint32_t a[4][4], b[4][2];
#pragma unroll
            for (int mf = 0; mf < 4; mf++) {
                uint32_t o = (uint32_t)((mbase + mf * 16 + ar) * 128 + kb2 + ak);
                ldm4(a[mf], Ab + sw(o));
            }
#pragma unroll
            for (int nfp = 0; nfp < 2; nfp++) {
                uint32_t o = (uint32_t)((nbase + nfp * 16 + br) * 128 + kb2 + bk);
                uint32_t r[4]; ldm4(r, Bb + sw(o));
                b[nfp * 2][0] = r[0]; b[nfp * 2][1] = r[1];
                b[nfp * 2 + 1][0] = r[2]; b[nfp * 2 + 1][1] = r[3];
            }
#pragma unroll
            for (int mf = 0; mf < 4; mf++)
#pragma unroll
                for (int nf = 0; nf < 4; nf++)
                    mma_f16(acc[mf][nf], a[mf], b[nf]);
        }
        __syncthreads();
    }

#pragma unroll
    for (int mf = 0; mf < 4; mf++) {
        const long r0g = m0 + mbase + mf * 16 + g;
#pragma unroll
        for (int nf = 0; nf < 4; nf++) {
            const int c = n0 + nbase + nf * 8 + t * 2;
            const float b0 = bias[c], b1 = bias[c + 1];
            float v0 = acc[mf][nf][0] + b0, v1 = acc[mf][nf][1] + b1;
            float v2 = acc[mf][nf][2] + b0, v3 = acc[mf][nf][3] + b1;
            __half2 h0 = __floats2half2_rn(v0 > 0.f ? v0 : 0.f, v1 > 0.f ? v1 : 0.f);
            __half2 h1 = __floats2half2_rn(v2 > 0.f ? v2 : 0.f, v3 > 0.f ? v3 : 0.f);
            *(__half2*)(out + r0g * D_ + c)       = h0;
            *(__half2*)(out + (r0g + 8) * D_ + c) = h1;
        }
    }
#undef HISSUE
}

// ---------------------------------------------------------------------------
// genT tile (device): melT[n][token] for 128-token tile `by`  (R6-proven config)
// ---------------------------------------------------------------------------
#define HG_BTILE 10240
#define HG_STAGE (H_ATILE + HG_BTILE)

__device__ void dev_genT(const float* __restrict__ bias, int by, char* dsm)
{
    const int tid  = threadIdx.x;
    const int warp = tid >> 5, lane = tid & 31;
    const int m0   = by * 128;

    const uint32_t base = (smem_u32(dsm) + 1023) & ~1023u;
    const uint32_t Aoff[2] = { base, base + HG_STAGE };
    const uint32_t Boff[2] = { base + H_ATILE, base + HG_STAGE + H_ATILE };

    const int r0  = tid >> 3;
    const int seg = (tid & 7) * 16;
    const char* ap[4]; uint32_t adst[4];
    const char* bp[3]; uint32_t bdst[3]; int bok[3];
#pragma unroll
    for (int i = 0; i < 4; i++) {
        const int r = r0 + i * 32;
        ap[i]   = (const char*)g_dect + (long)(m0 + r) * D_ * 2;
        adst[i] = sw((uint32_t)(r * 128 + seg));
    }
#pragma unroll
    for (int i = 0; i < 3; i++) {
        const int r = r0 + i * 32;
        bok[i]  = (r < MELS_);
        bp[i]   = (const char*)g_wgenT + (long)(bok[i] ? r : 0) * D_ * 2;
        bdst[i] = sw((uint32_t)(r * 128 + seg));
    }

#define GISSUE(c, s) do {                                                     \
        const int kb = (c) * 128;                                             \
        _Pragma("unroll")                                                     \
        for (int i = 0; i < 4; i++) cpa16(Aoff[s] + adst[i], ap[i] + kb + seg, 16); \
        _Pragma("unroll")                                                     \
        for (int i = 0; i < 3; i++)                                           \
            if (bok[i]) cpa16(Boff[s] + bdst[i], bp[i] + kb + seg, 16);       \
        asm volatile("cp.async.commit_group;");                               \
    } while (0)

    const int mbase = (warp & 3) * 32;
    const int nbase = (warp >> 2) * 40;
    const int li  = lane & 7, grp = lane >> 3;
    const int ar  = (grp & 1) * 8 + li,  ak = (grp >> 1) * 16;
    const int br  = (grp >> 1) * 8 + li, bk = (grp & 1) * 16;
    const int g = lane >> 2, t = lane & 3;

    float acc[2][5][4] = {};

    GISSUE(0, 0);
#pragma unroll 1
    for (int c = 0; c < 8; c++) {
        if (c < 7) {
            GISSUE(c + 1, (c + 1) & 1);
            asm volatile("cp.async.wait_group 1;");
        } else {
            asm volatile("cp.async.wait_group 0;");
        }
        __syncthreads();
        const uint32_t Ab = Aoff[c & 1], Bb = Boff[c & 1];
#pragma unroll
        for (int kk = 0; kk < 4; kk++) {
            const int kb2 = kk * 32;
            uint32_t a[2][4], b[5][2];
#pragma unroll
            for (int mf = 0; mf < 2; mf++) {
                uint32_t o = (uint32_t)((mbase + mf * 16 + ar) * 128 + kb2 + ak);
                ldm4(a[mf], Ab + sw(o));
            }
#pragma unroll
            for (int nfp = 0; nfp < 2; nfp++) {
                uint32_t o = (uint32_t)((nbase + nfp * 16 + br) * 128 + kb2 + bk);
                uint32_t r[4]; ldm4(r, Bb + sw(o));
                b[nfp * 2][0] = r[0]; b[nfp * 2][1] = r[1];
                b[nfp * 2 + 1][0] = r[2]; b[nfp * 2 + 1][1] = r[3];
            }
            {
                uint32_t o = (uint32_t)((nbase + 32 + li) * 128 + kb2 + (grp & 1) * 16);
                ldm2(b[4], Bb + sw(o));
            }
#pragma unroll
            for (int mf = 0; mf < 2; mf++)
#pragma unroll
                for (int nf = 0; nf < 5; nf++)
                    mma_f16(acc[mf][nf], a[mf], b[nf]);
        }
        __syncthreads();
    }

#pragma unroll
    for (int mf = 0; mf < 2; mf++) {
        const int tok = m0 + mbase + mf * 16 + g;
#pragma unroll
        for (int nf = 0; nf < 5; nf++) {
            const int n = nbase + nf * 8 + t * 2;
            const float b0 = bias[n], b1 = bias[n + 1];
            float* p0 = g_melT + (long)n * MT_ST;
            float* p1 = p0 + MT_ST;
            p0[tok]     = acc[mf][nf][0] + b0;
            p1[tok]     = acc[mf][nf][1] + b1;
            p0[tok + 8] = acc[mf][nf][2] + b0;
            p1[tok + 8] = acc[mf][nf][3] + b1;
        }
    }
#undef GISSUE
}

// ---------------------------------------------------------------------------
// mega kernel: P0 prep | P1 enc | P2 dec | P3 genT + dur | P4 expand
// ---------------------------------------------------------------------------
__global__ void __launch_bounds__(256, 1) mega_kernel(
    const int* __restrict__ src, const int* __restrict__ dur,
    const float* __restrict__ emb, const float* __restrict__ pos,
    const float* __restrict__ W_enc, const float* __restrict__ b_enc,
    const float* __restrict__ W_dur, const float* __restrict__ b_dur,
    const float* __restrict__ W_dec, const float* __restrict__ b_dec,
    const float* __restrict__ W_gen, const float* __restrict__ b_gen,
    float* __restrict__ mel, float* __restrict__ durp)
{
    extern __shared__ char dsm[];
    __shared__ float sbuf[32 * 33];
    const int cta = blockIdx.x;
    const int tid = threadIdx.x;

    // P0: prep
    for (int u = cta; u < NB_ALL; u += NCTA)
        prep_unit(u, sbuf, src, dur, emb, pos, W_enc, W_dec, W_gen, b_dec, b_gen);
    grid_bar(1 * NCTA);

    // P1: enc GEMM (128 tiles)
    dev_hgemm512(g_x, g_wencT, b_enc, g_enc, cta & 3, cta >> 2, dsm);
    grid_bar(2 * NCTA);

    // P2: dec GEMM
    dev_hgemm512(g_enc, g_wdecT, b_dec, g_dect, cta & 3, cta >> 2, dsm);
    grid_bar(3 * NCTA);

    // P3: genT (CTAs 0-31) + duration head (CTAs 32-127)
    if (cta < 32) {
        dev_genT(b_gen, cta, dsm);
    } else {
        const int warp = tid >> 5, lane = tid & 31;
        for (int u = cta - 32; u < M_ENC / 8; u += NCTA - 32) {
            const int m = u * 8 + warp;
            float s = 0.f;
            for (int k = lane; k < D_; k += 32)
                s += __half2float(g_enc[(long)m * D_ + k]) * W_dur[k];
#pragma unroll
            for (int o = 16; o; o >>= 1) s += __shfl_xor_sync(0xffffffffu, s, o);
            if (lane == 0) durp[m] = s + b_dur[0];
        }
    }
    grid_bar(4 * NCTA);

    // P4: expand — mel[b, n, t] = melT[n][tok(b, t)]
    {
        int* csum = (int*)sbuf;
        for (int u = cta; u < (T_ / 256) * B_; u += NCTA) {
            const int b  = u & (B_ - 1);
            const int t0 = (u >> 4) * 256;
            __syncthreads();
            csum[tid] = g_csum[b * L_ + tid];
            __syncthreads();
            const int t = t0 + tid;
            int lo = 0, hi = L_;
            while (lo < hi) {
                int mid = (lo + hi) >> 1;
                if (csum[mid] > t) hi = mid; else lo = mid + 1;
            }
            const int tok = (lo < L_) ? (b * L_ + lo) : M_ENC;
            float* out = mel + (long)b * MELS_ * T_ + t;
            const float* mt = g_melT + tok;
#pragma unroll 8
            for (int n = 0; n < MELS_; n++)
                out[(long)n * T_] = __ldg(mt + (long)n * MT_ST);
        }
    }

    // final arrival: last CTA resets the barrier counter for the next replay
    __syncthreads();
    if (tid == 0) {
        __threadfence();
        unsigned v = atomicAdd(&g_bar, 1u);
        if (v == 5u * NCTA - 1u) atomicExch(&g_bar, 0u);
    }
}

// ---------------------------------------------------------------------------
extern "C" void kernel_launch(void* const* d_in, const int* in_sizes, int n_in,
                              void* d_out, int out_size)
{
    const int* src = (const int*)d_in[0];
    const int* dur = (const int*)d_in[1];
    int p = 2;
    if (p < n_in && in_sizes[2] <= 4) p = 3;  // skip scalar T if materialized
    const float* emb   = (const float*)d_in[p + 0];
    const float* pos   = (const float*)d_in[p + 1];
    const float* W_enc = (const float*)d_in[p + 2];
    const float* b_enc = (const float*)d_in[p + 3];
    const float* W_dur = (const float*)d_in[p + 4];
    const float* b_dur = (const float*)d_in[p + 5];
    const float* W_dec = (const float*)d_in[p + 6];
    const float* b_dec = (const float*)d_in[p + 7];
    const float* W_gen = (const float*)d_in[p + 8];
    const float* b_gen = (const float*)d_in[p + 9];

    float* mel  = (float*)d_out;                         // [B, MELS, T]
    float* durp = (float*)d_out + (long)B_ * MELS_ * T_; // [B, L]

    static bool attr_done = false;
    if (!attr_done) {
        cudaFuncSetAttribute(mega_kernel, cudaFuncAttributeMaxDynamicSharedMemorySize,
                             SMEM512);
        attr_done = true;
    }

    mega_kernel<<<NCTA, 256, SMEM512>>>(src, dur, emb, pos, W_enc, b_enc,
                                        W_dur, b_dur, W_dec, b_dec, W_gen, b_gen,
                                        mel, durp);
}

// round 9
// speedup vs baseline: 1.4875x; 1.1234x over previous
#include <cuda_runtime.h>
#include <cuda_fp16.h>
#include <cstdint>

#define B_    16
#define L_    256
#define D_    512
#define MELS_ 80
#define T_    3072
#define M_ENC (B_ * L_)   // 4096
#define MT_ST 4160        // melT row stride (tokens 0..4095 + constant col 4096)
#define NCTA  256

// Scratch (__device__ globals; no allocation allowed)
__device__ __half g_x    [M_ENC * D_];
__device__ __half g_enc  [M_ENC * D_];
__device__ __half g_dect [M_ENC * D_];
__device__ int    g_csum [B_ * L_];
__device__ float  g_melTa[MELS_ * MT_ST];   // split-K partial 0 (k 0..255)
__device__ float  g_melTb[MELS_ * MT_ST];   // split-K partial 1 (k 256..511)
__device__ __half g_wencT[D_ * D_];
__device__ __half g_wdecT[D_ * D_];
__device__ __half g_wgenT[MELS_ * D_];
__device__ unsigned g_bar;                  // grid barrier counter (reset each run)

// ---------------------------------------------------------------------------
__device__ __forceinline__ uint32_t smem_u32(const void* p) {
    return (uint32_t)__cvta_generic_to_shared(p);
}
__device__ __forceinline__ void cpa16(uint32_t dst, const void* src, int srcsize) {
    asm volatile("cp.async.cg.shared.global [%0], [%1], 16, %2;"
                 :: "r"(dst), "l"(src), "r"(srcsize));
}
__device__ __forceinline__ uint32_t sw(uint32_t o) { return o ^ ((o >> 3) & 0x70); }

__device__ __forceinline__ void ldm4(uint32_t* r, uint32_t addr) {
    asm volatile("ldmatrix.sync.aligned.m8n8.x4.shared.b16 {%0,%1,%2,%3}, [%4];"
                 : "=r"(r[0]), "=r"(r[1]), "=r"(r[2]), "=r"(r[3]) : "r"(addr));
}
__device__ __forceinline__ void ldm2(uint32_t* r, uint32_t addr) {
    asm volatile("ldmatrix.sync.aligned.m8n8.x2.shared.b16 {%0,%1}, [%2];"
                 : "=r"(r[0]), "=r"(r[1]) : "r"(addr));
}
__device__ __forceinline__ void mma_f16(float* d, const uint32_t* a, const uint32_t* b) {
    asm volatile(
        "mma.sync.aligned.m16n8k16.row.col.f32.f16.f16.f32 "
        "{%0,%1,%2,%3},{%4,%5,%6,%7},{%8,%9},{%0,%1,%2,%3};"
        : "+f"(d[0]), "+f"(d[1]), "+f"(d[2]), "+f"(d[3])
        : "r"(a[0]), "r"(a[1]), "r"(a[2]), "r"(a[3]), "r"(b[0]), "r"(b[1]));
}

// grid barrier: all NCTA CTAs arrive; spin until count reaches target
__device__ __forceinline__ void grid_bar(unsigned target) {
    __syncthreads();
    if (threadIdx.x == 0) {
        __threadfence();
        atomicAdd(&g_bar, 1u);
        while (*(volatile unsigned*)&g_bar < target) __nanosleep(64);
        __threadfence();
    }
    __syncthreads();
}

// ---------------------------------------------------------------------------
// P0 prep units
// ---------------------------------------------------------------------------
#define NB_PREPX 2048
#define NB_T2    512
#define NB_TG    48
#define NB_SCAN  16
#define NB_ALL   (NB_PREPX + NB_T2 + NB_TG + NB_SCAN + 1)   // 2625

__device__ void prep_unit(int bid, float* sbuf,
    const int* __restrict__ src, const int* __restrict__ dur,
    const float* __restrict__ emb, const float* __restrict__ pos,
    const float* __restrict__ W_enc, const float* __restrict__ W_dec,
    const float* __restrict__ W_gen, const float* __restrict__ b_dec)
{
    const int tid = threadIdx.x;
    if (bid < NB_PREPX) {
        const long idx = (long)bid * 256 + tid;
        const int  m   = (int)(idx >> 7);
        const int  d4  = (int)(idx & 127) * 4;
        float4 e = *(const float4*)(emb + (long)src[m] * D_ + d4);
        float4 p = *(const float4*)(pos + (long)(m & (L_ - 1)) * D_ + d4);
        __half2 h0 = __floats2half2_rn(e.x + p.x, e.y + p.y);
        __half2 h1 = __floats2half2_rn(e.z + p.z, e.w + p.w);
        uint2 u = make_uint2(*(uint32_t*)&h0, *(uint32_t*)&h1);
        *(uint2*)(g_x + idx * 4) = u;
    } else if (bid < NB_PREPX + NB_T2) {
        const int id  = bid - NB_PREPX;
        const int z   = id >> 8;
        const int rem = id & 255;
        const int c0  = (rem & 15) * 32, r0 = (rem >> 4) * 32;
        const float* srcw = z ? W_dec : W_enc;
        __half* dst = z ? g_wdecT : g_wencT;
        const int tx = tid & 31, ty = tid >> 5;
        float (*tile)[33] = (float(*)[33])sbuf;
#pragma unroll
        for (int i = 0; i < 4; i++)
            tile[ty + i * 8][tx] = srcw[(r0 + ty + i * 8) * D_ + c0 + tx];
        __syncthreads();
#pragma unroll
        for (int i = 0; i < 4; i++)
            dst[(long)(c0 + ty + i * 8) * D_ + r0 + tx] =
                __float2half_rn(tile[tx][ty + i * 8]);
        __syncthreads();
    } else if (bid < NB_PREPX + NB_T2 + NB_TG) {
        const int id = bid - NB_PREPX - NB_T2;
        const int c0 = (id % 3) * 32, r0 = (id / 3) * 32;
        const int tx = tid & 31, ty = tid >> 5;
        float (*tile)[33] = (float(*)[33])sbuf;
#pragma unroll
        for (int i = 0; i < 4; i++) {
            int r = r0 + ty + i * 8, c = c0 + tx;
            if (c < MELS_) tile[ty + i * 8][tx] = W_gen[r * MELS_ + c];
        }
        __syncthreads();
#pragma unroll
        for (int i = 0; i < 4; i++) {
            int c = c0 + ty + i * 8, r = r0 + tx;
            if (c < MELS_)
                g_wgenT[(long)c * D_ + r] = __float2half_rn(tile[tx][ty + i * 8]);
        }
        __syncthreads();
    } else if (bid < NB_PREPX + NB_T2 + NB_TG + NB_SCAN) {
        const int b = bid - NB_PREPX - NB_T2 - NB_TG;
        int* csum = (int*)sbuf;
        csum[tid] = dur[b * L_ + tid];
        __syncthreads();
        for (int off = 1; off < L_; off <<= 1) {
            int x = (tid >= off) ? csum[tid - off] : 0;
            __syncthreads();
            csum[tid] += x;
            __syncthreads();
        }
        g_csum[b * L_ + tid] = csum[tid];
        __syncthreads();
    } else {
        // constant column: bias-free projection of relu(b_dec); half1 = 0
        float* rd = sbuf;
        for (int k = tid; k < D_; k += 256) {
            float v = b_dec[k]; rd[k] = v > 0.f ? v : 0.f;
        }
        __syncthreads();
        if (tid < MELS_) {
            float s = 0.f;
            for (int k = 0; k < D_; k++) s += rd[k] * W_gen[k * MELS_ + tid];
            g_melTa[tid * MT_ST + M_ENC] = s;
            g_melTb[tid * MT_ST + M_ENC] = 0.f;
        }
        __syncthreads();
    }
}

// ---------------------------------------------------------------------------
// hgemm tile 128m x 64n (device): out = fp16(relu(A @ Bt^T + bias))
// ---------------------------------------------------------------------------
#define A_T 16384
#define B_T 8192
#define STG (A_T + B_T)                 // 24576
#define GT_BT 10240
#define GT_STG (A_T + GT_BT)            // 26624
#define SMEM_DYN (2 * GT_STG + 1024)    // 54272

__device__ void dev_hgemm(const __half* __restrict__ A, const __half* __restrict__ Bt,
                          const float* __restrict__ bias, __half* __restrict__ out,
                          int bx, int by, char* dsm)
{
    const int tid  = threadIdx.x;
    const int warp = tid >> 5, lane = tid & 31;
    const int m0   = by * 128, n0 = bx * 64;

    const uint32_t base = (smem_u32(dsm) + 1023) & ~1023u;
    const uint32_t Aoff[2] = { base, base + STG };
    const uint32_t Boff[2] = { base + A_T, base + STG + A_T };

    const int r0  = tid >> 3;
    const int seg = (tid & 7) * 16;
    const char* ap[4];
    const char* bp[2];
    uint32_t dsta[4], dstb[2];
#pragma unroll
    for (int i = 0; i < 4; i++) {
        const int r = r0 + i * 32;
        ap[i]   = (const char*)A + (long)(m0 + r) * D_ * 2;
        dsta[i] = sw((uint32_t)(r * 128 + seg));
    }
#pragma unroll
    for (int i = 0; i < 2; i++) {
        const int r = r0 + i * 32;
        bp[i]   = (const char*)Bt + (long)(n0 + r) * D_ * 2;
        dstb[i] = sw((uint32_t)(r * 128 + seg));
    }

#define HISSUE(c, s) do {                                                     \
        const int kb = (c) * 128;                                             \
        _Pragma("unroll")                                                     \
        for (int i = 0; i < 4; i++) cpa16(Aoff[s] + dsta[i], ap[i] + kb + seg, 16); \
        _Pragma("unroll")                                                     \
        for (int i = 0; i < 2; i++) cpa16(Boff[s] + dstb[i], bp[i] + kb + seg, 16); \
        asm volatile("cp.async.commit_group;");                               \
    } while (0)

    const int mbase = (warp & 1) * 64;
    const int nbase = (warp >> 1) * 16;
    const int li  = lane & 7, grp = lane >> 3;
    const int ar  = (grp & 1) * 8 + li,  ak = (grp >> 1) * 16;
    const int br  = (grp >> 1) * 8 + li, bk = (grp & 1) * 16;
    const int g = lane >> 2, t = lane & 3;

    float acc[4][2][4] = {};

    HISSUE(0, 0);
#pragma unroll 1
    for (int c = 0; c < 8; c++) {
        if (c < 7) {
            HISSUE(c + 1, (c + 1) & 1);
            asm volatile("cp.async.wait_group 1;");
        } else {
            asm volatile("cp.async.wait_group 0;");
        }
        __syncthreads();
        const uint32_t Ab = Aoff[c & 1], Bb = Boff[c & 1];
#pragma unroll
        for (int kk = 0; kk < 4; kk++) {
            const int kb2 = kk * 32;
            uint32_t a[4][4], b[2][2];
#pragma unroll
            for (int mf = 0; mf < 4; mf++) {
                uint32_t o = (uint32_t)((mbase + mf * 16 + ar) * 128 + kb2 + ak);
                ldm4(a[mf], Ab + sw(o));
            }
            {
                uint32_t o = (uint32_t)((nbase + br) * 128 + kb2 + bk);
                uint32_t r[4]; ldm4(r, Bb + sw(o));
                b[0][0] = r[0]; b[0][1] = r[1];
                b[1][0] = r[2]; b[1][1] = r[3];
            }
#pragma unroll
            for (int mf = 0; mf < 4; mf++)
#pragma unroll
                for (int nf = 0; nf < 2; nf++)
                    mma_f16(acc[mf][nf], a[mf], b[nf]);
        }
        __syncthreads();
    }

#pragma unroll
    for (int mf = 0; mf < 4; mf++) {
        const long r0g = m0 + mbase + mf * 16 + g;
#pragma unroll
        for (int nf = 0; nf < 2; nf++) {
            const int c = n0 + nbase + nf * 8 + t * 2;
            const float b0 = bias[c], b1 = bias[c + 1];
            float v0 = acc[mf][nf][0] + b0, v1 = acc[mf][nf][1] + b1;
            float v2 = acc[mf][nf][2] + b0, v3 = acc[mf][nf][3] + b1;
            __half2 h0 = __floats2half2_rn(v0 > 0.f ? v0 : 0.f, v1 > 0.f ? v1 : 0.f);
            __half2 h1 = __floats2half2_rn(v2 > 0.f ? v2 : 0.f, v3 > 0.f ? v3 : 0.f);
            *(__half2*)(out + r0g * D_ + c)       = h0;
            *(__half2*)(out + (r0g + 8) * D_ + c) = h1;
        }
    }
#undef HISSUE
}

// ---------------------------------------------------------------------------
// genT split-K tile (device): partial melT[n][token] over K half `kh`
//   128-token tile, 8 warps = 4m x 2n, N = 80, 4 K-chunks (K = 256)
// ---------------------------------------------------------------------------
__device__ void dev_genT(int by, int kh, float* __restrict__ melT, char* dsm)
{
    const int tid  = threadIdx.x;
    const int warp = tid >> 5, lane = tid & 31;
    const int m0   = by * 128;
    const int kb0  = kh * 512;           // byte offset of this K half

    const uint32_t base = (smem_u32(dsm) + 1023) & ~1023u;
    const uint32_t Aoff[2] = { base, base + GT_STG };
    const uint32_t Boff[2] = { base + A_T, base + GT_STG + A_T };

    const int r0  = tid >> 3;
    const int seg = (tid & 7) * 16;
    const char* ap[4]; uint32_t adst[4];
    const char* bp[3]; uint32_t bdst[3]; int bok[3];
#pragma unroll
    for (int i = 0; i < 4; i++) {
        const int r = r0 + i * 32;
        ap[i]   = (const char*)g_dect + (long)(m0 + r) * D_ * 2;
        adst[i] = sw((uint32_t)(r * 128 + seg));
    }
#pragma unroll
    for (int i = 0; i < 3; i++) {
        const int r = r0 + i * 32;
        bok[i]  = (r < MELS_);
        bp[i]   = (const char*)g_wgenT + (long)(bok[i] ? r : 0) * D_ * 2;
        bdst[i] = sw((uint32_t)(r * 128 + seg));
    }

#define GISSUE(c, s) do {                                                     \
        const int kb = kb0 + (c) * 128;                                       \
        _Pragma("unroll")                                                     \
        for (int i = 0; i < 4; i++) cpa16(Aoff[s] + adst[i], ap[i] + kb + seg, 16); \
        _Pragma("unroll")                                                     \
        for (int i = 0; i < 3; i++)                                           \
            if (bok[i]) cpa16(Boff[s] + bdst[i], bp[i] + kb + seg, 16);       \
        asm volatile("cp.async.commit_group;");                               \
    } while (0)

    const int mbase = (warp & 3) * 32;
    const int nbase = (warp >> 2) * 40;
    const int li  = lane & 7, grp = lane >> 3;
    const int ar  = (grp & 1) * 8 + li,  ak = (grp >> 1) * 16;
    const int br  = (grp >> 1) * 8 + li, bk = (grp & 1) * 16;
    const int g = lane >> 2, t = lane & 3;

    float acc[2][5][4] = {};

    GISSUE(0, 0);
#pragma unroll 1
    for (int c = 0; c < 4; c++) {
        if (c < 3) {
            GISSUE(c + 1, (c + 1) & 1);
            asm volatile("cp.async.wait_group 1;");
        } else {
            asm volatile("cp.async.wait_group 0;");
        }
        __syncthreads();
        const uint32_t Ab = Aoff[c & 1], Bb = Boff[c & 1];
#pragma unroll
        for (int kk = 0; kk < 4; kk++) {
            const int kb2 = kk * 32;
            uint32_t a[2][4], b[5][2];
#pragma unroll
            for (int mf = 0; mf < 2; mf++) {
                uint32_t o = (uint32_t)((mbase + mf * 16 + ar) * 128 + kb2 + ak);
                ldm4(a[mf], Ab + sw(o));
            }
#pragma unroll
            for (int nfp = 0; nfp < 2; nfp++) {
                uint32_t o = (uint32_t)((nbase + nfp * 16 + br) * 128 + kb2 + bk);
                uint32_t r[4]; ldm4(r, Bb + sw(o));
                b[nfp * 2][0] = r[0]; b[nfp * 2][1] = r[1];
                b[nfp * 2 + 1][0] = r[2]; b[nfp * 2 + 1][1] = r[3];
            }
            {
                uint32_t o = (uint32_t)((nbase + 32 + li) * 128 + kb2 + (grp & 1) * 16);
                ldm2(b[4], Bb + sw(o));
            }
#pragma unroll
            for (int mf = 0; mf < 2; mf++)
#pragma unroll
                for (int nf = 0; nf < 5; nf++)
                    mma_f16(acc[mf][nf], a[mf], b[nf]);
        }
        __syncthreads();
    }

#pragma unroll
    for (int mf = 0; mf < 2; mf++) {
        const int tok = m0 + mbase + mf * 16 + g;
#pragma unroll
        for (int nf = 0; nf < 5; nf++) {
            const int n = nbase + nf * 8 + t * 2;
            float* p0 = melT + (long)n * MT_ST;
            float* p1 = p0 + MT_ST;
            p0[tok]     = acc[mf][nf][0];
            p1[tok]     = acc[mf][nf][1];
            p0[tok + 8] = acc[mf][nf][2];
            p1[tok + 8] = acc[mf][nf][3];
        }
    }
#undef GISSUE
}

// ---------------------------------------------------------------------------
// mega kernel: P0 prep | P1 enc | P2 dec | P3 genT(split-K) + dur | P4 expand
// ---------------------------------------------------------------------------
__global__ void __launch_bounds__(256, 2) mega_kernel(
    const int* __restrict__ src, const int* __restrict__ dur,
    const float* __restrict__ emb, const float* __restrict__ pos,
    const float* __restrict__ W_enc, const float* __restrict__ b_enc,
    const float* __restrict__ W_dur, const float* __restrict__ b_dur,
    const float* __restrict__ W_dec, const float* __restrict__ b_dec,
    const float* __restrict__ W_gen, const float* __restrict__ b_gen,
    float* __restrict__ mel, float* __restrict__ durp)
{
    extern __shared__ char dsm[];
    __shared__ float sbuf[32 * 33];
    __shared__ float bsh[MELS_];
    const int cta = blockIdx.x;
    const int tid = threadIdx.x;

    // P0: prep
    for (int u = cta; u < NB_ALL; u += NCTA)
        prep_unit(u, sbuf, src, dur, emb, pos, W_enc, W_dec, W_gen, b_dec);
    grid_bar(1 * NCTA);

    // P1: enc GEMM (256 tiles of 128x64)
    dev_hgemm(g_x, g_wencT, b_enc, g_enc, cta & 7, cta >> 3, dsm);
    grid_bar(2 * NCTA);

    // P2: dec GEMM
    dev_hgemm(g_enc, g_wdecT, b_dec, g_dect, cta & 7, cta >> 3, dsm);
    grid_bar(3 * NCTA);

    // P3: genT split-K (CTAs 0-63) + duration head (CTAs 64-255)
    if (cta < 64) {
        dev_genT(cta >> 1, cta & 1, (cta & 1) ? g_melTb : g_melTa, dsm);
    } else {
        const int warp = tid >> 5, lane = tid & 31;
        for (int u = cta - 64; u < M_ENC / 8; u += NCTA - 64) {
            const int m = u * 8 + warp;
            float s = 0.f;
            for (int k = lane; k < D_; k += 32)
                s += __half2float(g_enc[(long)m * D_ + k]) * W_dur[k];
#pragma unroll
            for (int o = 16; o; o >>= 1) s += __shfl_xor_sync(0xffffffffu, s, o);
            if (lane == 0) durp[m] = s + b_dur[0];
        }
    }
    grid_bar(4 * NCTA);

    // P4: expand — mel[b, n, t] = melTa[n][tok] + melTb[n][tok] + b_gen[n]
    {
        int* csum = (int*)sbuf;
        if (tid < MELS_) bsh[tid] = b_gen[tid];
        for (int u = cta; u < (T_ / 256) * B_; u += NCTA) {
            const int b  = u & (B_ - 1);
            const int t0 = (u >> 4) * 256;
            __syncthreads();
            csum[tid] = g_csum[b * L_ + tid];
            __syncthreads();
            const int t = t0 + tid;
            int lo = 0, hi = L_;
            while (lo < hi) {
                int mid = (lo + hi) >> 1;
                if (csum[mid] > t) hi = mid; else lo = mid + 1;
            }
            const int tok = (lo < L_) ? (b * L_ + lo) : M_ENC;
            float* out = mel + (long)b * MELS_ * T_ + t;
            const float* ma = g_melTa + tok;
            const float* mb = g_melTb + tok;
#pragma unroll 8
            for (int n = 0; n < MELS_; n++)
                out[(long)n * T_] =
                    __ldg(ma + (long)n * MT_ST) + __ldg(mb + (long)n * MT_ST) + bsh[n];
        }
    }

    // final arrival: last CTA resets the barrier counter for the next replay
    __syncthreads();
    if (tid == 0) {
        __threadfence();
        unsigned v = atomicAdd(&g_bar, 1u);
        if (v == 5u * NCTA - 1u) atomicExch(&g_bar, 0u);
    }
}

// ---------------------------------------------------------------------------
extern "C" void kernel_launch(void* const* d_in, const int* in_sizes, int n_in,
                              void* d_out, int out_size)
{
    const int* src = (const int*)d_in[0];
    const int* dur = (const int*)d_in[1];
    int p = 2;
    if (p < n_in && in_sizes[2] <= 4) p = 3;  // skip scalar T if materialized
    const float* emb   = (const float*)d_in[p + 0];
    const float* pos   = (const float*)d_in[p + 1];
    const float* W_enc = (const float*)d_in[p + 2];
    const float* b_enc = (const float*)d_in[p + 3];
    const float* W_dur = (const float*)d_in[p + 4];
    const float* b_dur = (const float*)d_in[p + 5];
    const float* W_dec = (const float*)d_in[p + 6];
    const float* b_dec = (const float*)d_in[p + 7];
    const float* W_gen = (const float*)d_in[p + 8];
    const float* b_gen = (const float*)d_in[p + 9];

    float* mel  = (float*)d_out;                         // [B, MELS, T]
    float* durp = (float*)d_out + (long)B_ * MELS_ * T_; // [B, L]

    static bool attr_done = false;
    if (!attr_done) {
        cudaFuncSetAttribute(mega_kernel, cudaFuncAttributeMaxDynamicSharedMemorySize,
                             SMEM_DYN);
        attr_done = true;
    }

    mega_kernel<<<NCTA, 256, SMEM_DYN>>>(src, dur, emb, pos, W_enc, b_enc,
                                         W_dur, b_dur, W_dec, b_dec, W_gen, b_gen,
                                         mel, durp);
}

// round 10
// speedup vs baseline: 1.5152x; 1.0186x over previous
#include <cuda_runtime.h>
#include <cuda_fp16.h>
#include <cstdint>

#define B_    16
#define L_    256
#define D_    512
#define MELS_ 80
#define T_    3072
#define M_ENC (B_ * L_)   // 4096
#define MT_ST 4160        // melT row stride (tokens 0..4095 + constant col 4096)
#define NCTA  256

// Scratch (__device__ globals; no allocation allowed)
__device__ __half g_x    [M_ENC * D_];
__device__ __half g_enc  [M_ENC * D_];
__device__ __half g_dect [M_ENC * D_];
__device__ int    g_csum [B_ * L_];
__device__ float  g_melTa[MELS_ * MT_ST];   // split-K partial 0 (k 0..255)
__device__ float  g_melTb[MELS_ * MT_ST];   // split-K partial 1 (k 256..511)
__device__ __half g_wencT[D_ * D_];
__device__ __half g_wdecT[D_ * D_];
__device__ __half g_wgenT[MELS_ * D_];
__device__ unsigned g_bar;                  // grid barrier counter
__device__ int g_flagE[32];                 // enc row-block ready (8 arrivals)
__device__ int g_flagD[32];                 // dec row-block ready (8 arrivals)
__device__ int g_flagB[16];                 // melT batch ready (4 arrivals)

// ---------------------------------------------------------------------------
__device__ __forceinline__ uint32_t smem_u32(const void* p) {
    return (uint32_t)__cvta_generic_to_shared(p);
}
__device__ __forceinline__ void cpa16(uint32_t dst, const void* src, int srcsize) {
    asm volatile("cp.async.cg.shared.global [%0], [%1], 16, %2;"
                 :: "r"(dst), "l"(src), "r"(srcsize));
}
__device__ __forceinline__ uint32_t sw(uint32_t o) { return o ^ ((o >> 3) & 0x70); }

__device__ __forceinline__ void ldm4(uint32_t* r, uint32_t addr) {
    asm volatile("ldmatrix.sync.aligned.m8n8.x4.shared.b16 {%0,%1,%2,%3}, [%4];"
                 : "=r"(r[0]), "=r"(r[1]), "=r"(r[2]), "=r"(r[3]) : "r"(addr));
}
__device__ __forceinline__ void ldm2(uint32_t* r, uint32_t addr) {
    asm volatile("ldmatrix.sync.aligned.m8n8.x2.shared.b16 {%0,%1}, [%2];"
                 : "=r"(r[0]), "=r"(r[1]) : "r"(addr));
}
__device__ __forceinline__ void mma_f16(float* d, const uint32_t* a, const uint32_t* b) {
    asm volatile(
        "mma.sync.aligned.m16n8k16.row.col.f32.f16.f16.f32 "
        "{%0,%1,%2,%3},{%4,%5,%6,%7},{%8,%9},{%0,%1,%2,%3};"
        : "+f"(d[0]), "+f"(d[1]), "+f"(d[2]), "+f"(d[3])
        : "r"(a[0]), "r"(a[1]), "r"(a[2]), "r"(a[3]), "r"(b[0]), "r"(b[1]));
}

// release-signal: all threads fence their writes, then one arrival
__device__ __forceinline__ void signal(int* f) {
    __threadfence();
    __syncthreads();
    if (threadIdx.x == 0) atomicAdd(f, 1);
}
// acquire-wait: spin until count reaches target
__device__ __forceinline__ void waitf(int* f, int tgt) {
    if (threadIdx.x == 0) {
        while (*(volatile int*)f < tgt) __nanosleep(32);
        __threadfence();
    }
    __syncthreads();
}
// full grid barrier (P0 only)
__device__ __forceinline__ void grid_bar(unsigned target) {
    __syncthreads();
    if (threadIdx.x == 0) {
        __threadfence();
        atomicAdd(&g_bar, 1u);
        while (*(volatile unsigned*)&g_bar < target) __nanosleep(64);
        __threadfence();
    }
    __syncthreads();
}

// ---------------------------------------------------------------------------
// P0 prep units
// ---------------------------------------------------------------------------
#define NB_PREPX 2048
#define NB_T2    512
#define NB_TG    48
#define NB_SCAN  16
#define NB_ALL   (NB_PREPX + NB_T2 + NB_TG + NB_SCAN + 1)   // 2625

__device__ void prep_unit(int bid, float* sbuf,
    const int* __restrict__ src, const int* __restrict__ dur,
    const float* __restrict__ emb, const float* __restrict__ pos,
    const float* __restrict__ W_enc, const float* __restrict__ W_dec,
    const float* __restrict__ W_gen, const float* __restrict__ b_dec)
{
    const int tid = threadIdx.x;
    if (bid < NB_PREPX) {
        const long idx = (long)bid * 256 + tid;
        const int  m   = (int)(idx >> 7);
        const int  d4  = (int)(idx & 127) * 4;
        float4 e = *(const float4*)(emb + (long)src[m] * D_ + d4);
        float4 p = *(const float4*)(pos + (long)(m & (L_ - 1)) * D_ + d4);
        __half2 h0 = __floats2half2_rn(e.x + p.x, e.y + p.y);
        __half2 h1 = __floats2half2_rn(e.z + p.z, e.w + p.w);
        uint2 u = make_uint2(*(uint32_t*)&h0, *(uint32_t*)&h1);
        *(uint2*)(g_x + idx * 4) = u;
    } else if (bid < NB_PREPX + NB_T2) {
        const int id  = bid - NB_PREPX;
        const int z   = id >> 8;
        const int rem = id & 255;
        const int c0  = (rem & 15) * 32, r0 = (rem >> 4) * 32;
        const float* srcw = z ? W_dec : W_enc;
        __half* dst = z ? g_wdecT : g_wencT;
        const int tx = tid & 31, ty = tid >> 5;
        float (*tile)[33] = (float(*)[33])sbuf;
#pragma unroll
        for (int i = 0; i < 4; i++)
            tile[ty + i * 8][tx] = srcw[(r0 + ty + i * 8) * D_ + c0 + tx];
        __syncthreads();
#pragma unroll
        for (int i = 0; i < 4; i++)
            dst[(long)(c0 + ty + i * 8) * D_ + r0 + tx] =
                __float2half_rn(tile[tx][ty + i * 8]);
        __syncthreads();
    } else if (bid < NB_PREPX + NB_T2 + NB_TG) {
        const int id = bid - NB_PREPX - NB_T2;
        const int c0 = (id % 3) * 32, r0 = (id / 3) * 32;
        const int tx = tid & 31, ty = tid >> 5;
        float (*tile)[33] = (float(*)[33])sbuf;
#pragma unroll
        for (int i = 0; i < 4; i++) {
            int r = r0 + ty + i * 8, c = c0 + tx;
            if (c < MELS_) tile[ty + i * 8][tx] = W_gen[r * MELS_ + c];
        }
        __syncthreads();
#pragma unroll
        for (int i = 0; i < 4; i++) {
            int c = c0 + ty + i * 8, r = r0 + tx;
            if (c < MELS_)
                g_wgenT[(long)c * D_ + r] = __float2half_rn(tile[tx][ty + i * 8]);
        }
        __syncthreads();
    } else if (bid < NB_PREPX + NB_T2 + NB_TG + NB_SCAN) {
        const int b = bid - NB_PREPX - NB_T2 - NB_TG;
        int* csum = (int*)sbuf;
        csum[tid] = dur[b * L_ + tid];
        __syncthreads();
        for (int off = 1; off < L_; off <<= 1) {
            int x = (tid >= off) ? csum[tid - off] : 0;
            __syncthreads();
            csum[tid] += x;
            __syncthreads();
        }
        g_csum[b * L_ + tid] = csum[tid];
        __syncthreads();
    } else {
        // constant column: bias-free projection of relu(b_dec); half1 = 0
        float* rd = sbuf;
        for (int k = tid; k < D_; k += 256) {
            float v = b_dec[k]; rd[k] = v > 0.f ? v : 0.f;
        }
        __syncthreads();
        if (tid < MELS_) {
            float s = 0.f;
            for (int k = 0; k < D_; k++) s += rd[k] * W_gen[k * MELS_ + tid];
            g_melTa[tid * MT_ST + M_ENC] = s;
            g_melTb[tid * MT_ST + M_ENC] = 0.f;
        }
        __syncthreads();
    }
}

// ---------------------------------------------------------------------------
// hgemm tile 128m x 64n (device): out = fp16(relu(A @ Bt^T + bias))
// ---------------------------------------------------------------------------
#define A_T 16384
#define B_T 8192
#define STG (A_T + B_T)                 // 24576
#define GT_BT 10240
#define GT_STG (A_T + GT_BT)            // 26624
#define SMEM_DYN (2 * GT_STG + 1024)    // 54272

__device__ void dev_hgemm(const __half* __restrict__ A, const __half* __restrict__ Bt,
                          const float* __restrict__ bias, __half* __restrict__ out,
                          int bx, int by, char* dsm)
{
    const int tid  = threadIdx.x;
    const int warp = tid >> 5, lane = tid & 31;
    const int m0   = by * 128, n0 = bx * 64;

    const uint32_t base = (smem_u32(dsm) + 1023) & ~1023u;
    const uint32_t Aoff[2] = { base, base + STG };
    const uint32_t Boff[2] = { base + A_T, base + STG + A_T };

    const int r0  = tid >> 3;
    const int seg = (tid & 7) * 16;
    const char* ap[4];
    const char* bp[2];
    uint32_t dsta[4], dstb[2];
#pragma unroll
    for (int i = 0; i < 4; i++) {
        const int r = r0 + i * 32;
        ap[i]   = (const char*)A + (long)(m0 + r) * D_ * 2;
        dsta[i] = sw((uint32_t)(r * 128 + seg));
    }
#pragma unroll
    for (int i = 0; i < 2; i++) {
        const int r = r0 + i * 32;
        bp[i]   = (const char*)Bt + (long)(n0 + r) * D_ * 2;
        dstb[i] = sw((uint32_t)(r * 128 + seg));
    }

#define HISSUE(c, s) do {                                                     \
        const int kb = (c) * 128;                                             \
        _Pragma("unroll")                                                     \
        for (int i = 0; i < 4; i++) cpa16(Aoff[s] + dsta[i], ap[i] + kb + seg, 16); \
        _Pragma("unroll")                                                     \
        for (int i = 0; i < 2; i++) cpa16(Boff[s] + dstb[i], bp[i] + kb + seg, 16); \
        asm volatile("cp.async.commit_group;");                               \
    } while (0)

    const int mbase = (warp & 1) * 64;
    const int nbase = (warp >> 1) * 16;
    const int li  = lane & 7, grp = lane >> 3;
    const int ar  = (grp & 1) * 8 + li,  ak = (grp >> 1) * 16;
    const int br  = (grp >> 1) * 8 + li, bk = (grp & 1) * 16;
    const int g = lane >> 2, t = lane & 3;

    float acc[4][2][4] = {};

    HISSUE(0, 0);
#pragma unroll 1
    for (int c = 0; c < 8; c++) {
        if (c < 7) {
            HISSUE(c + 1, (c + 1) & 1);
            asm volatile("cp.async.wait_group 1;");
        } else {
            asm volatile("cp.async.wait_group 0;");
        }
        __syncthreads();
        const uint32_t Ab = Aoff[c & 1], Bb = Boff[c & 1];
#pragma unroll
        for (int kk = 0; kk < 4; kk++) {
            const int kb2 = kk * 32;
            uint32_t a[4][4], b[2][2];
#pragma unroll
            for (int mf = 0; mf < 4; mf++) {
                uint32_t o = (uint32_t)((mbase + mf * 16 + ar) * 128 + kb2 + ak);
                ldm4(a[mf], Ab + sw(o));
            }
            {
                uint32_t o = (uint32_t)((nbase + br) * 128 + kb2 + bk);
                uint32_t r[4]; ldm4(r, Bb + sw(o));
                b[0][0] = r[0]; b[0][1] = r[1];
                b[1][0] = r[2]; b[1][1] = r[3];
            }
#pragma unroll
            for (int mf = 0; mf < 4; mf++)
#pragma unroll
                for (int nf = 0; nf < 2; nf++)
                    mma_f16(acc[mf][nf], a[mf], b[nf]);
        }
        __syncthreads();
    }

#pragma unroll
    for (int mf = 0; mf < 4; mf++) {
        const long r0g = m0 + mbase + mf * 16 + g;
#pragma unroll
        for (int nf = 0; nf < 2; nf++) {
            const int c = n0 + nbase + nf * 8 + t * 2;
            const float b0 = bias[c], b1 = bias[c + 1];
            float v0 = acc[mf][nf][0] + b0, v1 = acc[mf][nf][1] + b1;
            float v2 = acc[mf][nf][2] + b0, v3 = acc[mf][nf][3] + b1;
            __half2 h0 = __floats2half2_rn(v0 > 0.f ? v0 : 0.f, v1 > 0.f ? v1 : 0.f);
            __half2 h1 = __floats2half2_rn(v2 > 0.f ? v2 : 0.f, v3 > 0.f ? v3 : 0.f);
            *(__half2*)(out + r0g * D_ + c)       = h0;
            *(__half2*)(out + (r0g + 8) * D_ + c) = h1;
        }
    }
#undef HISSUE
}

// ---------------------------------------------------------------------------
// genT split-K tile (device): partial melT[n][token] over K half `kh`
// ---------------------------------------------------------------------------
__device__ void dev_genT(int by, int kh, float* __restrict__ melT, char* dsm)
{
    const int tid  = threadIdx.x;
    const int warp = tid >> 5, lane = tid & 31;
    const int m0   = by * 128;
    const int kb0  = kh * 512;           // byte offset of this K half

    const uint32_t base = (smem_u32(dsm) + 1023) & ~1023u;
    const uint32_t Aoff[2] = { base, base + GT_STG };
    const uint32_t Boff[2] = { base + A_T, base + GT_STG + A_T };

    const int r0  = tid >> 3;
    const int seg = (tid & 7) * 16;
    const char* ap[4]; uint32_t adst[4];
    const char* bp[3]; uint32_t bdst[3]; int bok[3];
#pragma unroll
    for (int i = 0; i < 4; i++) {
        const int r = r0 + i * 32;
        ap[i]   = (const char*)g_dect + (long)(m0 + r) * D_ * 2;
        adst[i] = sw((uint32_t)(r * 128 + seg));
    }
#pragma unroll
    for (int i = 0; i < 3; i++) {
        const int r = r0 + i * 32;
        bok[i]  = (r < MELS_);
        bp[i]   = (const char*)g_wgenT + (long)(bok[i] ? r : 0) * D_ * 2;
        bdst[i] = sw((uint32_t)(r * 128 + seg));
    }

#define GISSUE(c, s) do {                                                     \
        const int kb = kb0 + (c) * 128;                                       \
        _Pragma("unroll")                                                     \
        for (int i = 0; i < 4; i++) cpa16(Aoff[s] + adst[i], ap[i] + kb + seg, 16); \
        _Pragma("unroll")                                                     \
        for (int i = 0; i < 3; i++)                                           \
            if (bok[i]) cpa16(Boff[s] + bdst[i], bp[i] + kb + seg, 16);       \
        asm volatile("cp.async.commit_group;");                               \
    } while (0)

    const int mbase = (warp & 3) * 32;
    const int nbase = (warp >> 2) * 40;
    const int li  = lane & 7, grp = lane >> 3;
    const int ar  = (grp & 1) * 8 + li,  ak = (grp >> 1) * 16;
    const int br  = (grp >> 1) * 8 + li, bk = (grp & 1) * 16;
    const int g = lane >> 2, t = lane & 3;

    float acc[2][5][4] = {};

    GISSUE(0, 0);
#pragma unroll 1
    for (int c = 0; c < 4; c++) {
        if (c < 3) {
            GISSUE(c + 1, (c + 1) & 1);
            asm volatile("cp.async.wait_group 1;");
        } else {
            asm volatile("cp.async.wait_group 0;");
        }
        __syncthreads();
        const uint32_t Ab = Aoff[c & 1], Bb = Boff[c & 1];
#pragma unroll
        for (int kk = 0; kk < 4; kk++) {
            const int kb2 = kk * 32;
            uint32_t a[2][4], b[5][2];
#pragma unroll
            for (int mf = 0; mf < 2; mf++) {
                uint32_t o = (uint32_t)((mbase + mf * 16 + ar) * 128 + kb2 + ak);
                ldm4(a[mf], Ab + sw(o));
            }
#pragma unroll
            for (int nfp = 0; nfp < 2; nfp++) {
                uint32_t o = (uint32_t)((nbase + nfp * 16 + br) * 128 + kb2 + bk);
                uint32_t r[4]; ldm4(r, Bb + sw(o));
                b[nfp * 2][0] = r[0]; b[nfp * 2][1] = r[1];
                b[nfp * 2 + 1][0] = r[2]; b[nfp * 2 + 1][1] = r[3];
            }
            {
                uint32_t o = (uint32_t)((nbase + 32 + li) * 128 + kb2 + (grp & 1) * 16);
                ldm2(b[4], Bb + sw(o));
            }
#pragma unroll
            for (int mf = 0; mf < 2; mf++)
#pragma unroll
                for (int nf = 0; nf < 5; nf++)
                    mma_f16(acc[mf][nf], a[mf], b[nf]);
        }
        __syncthreads();
    }

#pragma unroll
    for (int mf = 0; mf < 2; mf++) {
        const int tok = m0 + mbase + mf * 16 + g;
#pragma unroll
        for (int nf = 0; nf < 5; nf++) {
            const int n = nbase + nf * 8 + t * 2;
            float* p0 = melT + (long)n * MT_ST;
            float* p1 = p0 + MT_ST;
            p0[tok]     = acc[mf][nf][0];
            p1[tok]     = acc[mf][nf][1];
            p0[tok + 8] = acc[mf][nf][2];
            p1[tok + 8] = acc[mf][nf][3];
        }
    }
#undef GISSUE
}

// ---------------------------------------------------------------------------
// mega kernel, dataflow version:
//   P0 prep | barrier | enc -> flagE | dec -> flagD | genT -> flagB / dur | expand
// ---------------------------------------------------------------------------
__global__ void __launch_bounds__(256, 2) mega_kernel(
    const int* __restrict__ src, const int* __restrict__ dur,
    const float* __restrict__ emb, const float* __restrict__ pos,
    const float* __restrict__ W_enc, const float* __restrict__ b_enc,
    const float* __restrict__ W_dur, const float* __restrict__ b_dur,
    const float* __restrict__ W_dec, const float* __restrict__ b_dec,
    const float* __restrict__ W_gen, const float* __restrict__ b_gen,
    float* __restrict__ mel, float* __restrict__ durp)
{
    extern __shared__ char dsm[];
    __shared__ float sbuf[32 * 33];
    __shared__ float bsh[MELS_];
    const int cta = blockIdx.x;
    const int tid = threadIdx.x;

    // P0: prep (needs the single global barrier — everything depends on it)
    for (int u = cta; u < NB_ALL; u += NCTA)
        prep_unit(u, sbuf, src, dur, emb, pos, W_enc, W_dec, W_gen, b_dec);
    grid_bar(NCTA);

    // enc GEMM: tile (cta&7, cta>>3); signal row-block readiness
    dev_hgemm(g_x, g_wencT, b_enc, g_enc, cta & 7, cta >> 3, dsm);
    signal(&g_flagE[cta >> 3]);

    // dec GEMM: same tile coords; needs enc row-block (8 producers)
    waitf(&g_flagE[cta >> 3], 8);
    dev_hgemm(g_enc, g_wdecT, b_dec, g_dect, cta & 7, cta >> 3, dsm);
    signal(&g_flagD[cta >> 3]);

    if (cta < 64) {
        // genT split-K: tile by = cta>>1, K half = cta&1
        waitf(&g_flagD[cta >> 1], 8);
        dev_genT(cta >> 1, cta & 1, (cta & 1) ? g_melTb : g_melTa, dsm);
        signal(&g_flagB[cta >> 2]);
    } else {
        // duration head: units of 8 rows; wait on the enc row-block per unit
        const int warp = tid >> 5, lane = tid & 31;
        for (int u = cta - 64; u < M_ENC / 8; u += NCTA - 64) {
            waitf(&g_flagE[u >> 4], 8);
            const int m = u * 8 + warp;
            float s = 0.f;
            for (int k = lane; k < D_; k += 32)
                s += __half2float(g_enc[(long)m * D_ + k]) * W_dur[k];
#pragma unroll
            for (int o = 16; o; o >>= 1) s += __shfl_xor_sync(0xffffffffu, s, o);
            if (lane == 0) durp[m] = s + b_dur[0];
        }

        // expand: one unit per CTA (192 units on CTAs 64..255)
        const int u  = cta - 64;
        const int b  = u & (B_ - 1);
        const int t0 = (u >> 4) * 256;
        waitf(&g_flagB[b], 4);
        int* csum = (int*)sbuf;
        if (tid < MELS_) bsh[tid] = b_gen[tid];
        csum[tid] = g_csum[b * L_ + tid];
        __syncthreads();
        const int t = t0 + tid;
        int lo = 0, hi = L_;
        while (lo < hi) {
            int mid = (lo + hi) >> 1;
            if (csum[mid] > t) hi = mid; else lo = mid + 1;
        }
        const int tok = (lo < L_) ? (b * L_ + lo) : M_ENC;
        float* out = mel + (long)b * MELS_ * T_ + t;
        const float* ma = g_melTa + tok;
        const float* mb = g_melTb + tok;
#pragma unroll 8
        for (int n = 0; n < MELS_; n++)
            out[(long)n * T_] =
                __ldg(ma + (long)n * MT_ST) + __ldg(mb + (long)n * MT_ST) + bsh[n];
    }

    // final arrival: the (2*NCTA)th arrival resets barrier + flags.
    // Safe: it cannot happen until every CTA has passed all its waits.
    __threadfence();
    __syncthreads();
    if (tid == 0) {
        unsigned v = atomicAdd(&g_bar, 1u);
        if (v == 2u * NCTA - 1u) {
            for (int i = 0; i < 32; i++) { g_flagE[i] = 0; g_flagD[i] = 0; }
            for (int i = 0; i < 16; i++) g_flagB[i] = 0;
            atomicExch(&g_bar, 0u);
        }
    }
}

// ---------------------------------------------------------------------------
extern "C" void kernel_launch(void* const* d_in, const int* in_sizes, int n_in,
                              void* d_out, int out_size)
{
    const int* src = (const int*)d_in[0];
    const int* dur = (const int*)d_in[1];
    int p = 2;
    if (p < n_in && in_sizes[2] <= 4) p = 3;  // skip scalar T if materialized
    const float* emb   = (const float*)d_in[p + 0];
    const float* pos   = (const float*)d_in[p + 1];
    const float* W_enc = (const float*)d_in[p + 2];
    const float* b_enc = (const float*)d_in[p + 3];
    const float* W_dur = (const float*)d_in[p + 4];
    const float* b_dur = (const float*)d_in[p + 5];
    const float* W_dec = (const float*)d_in[p + 6];
    const float* b_dec = (const float*)d_in[p + 7];
    const float* W_gen = (const float*)d_in[p + 8];
    const float* b_gen = (const float*)d_in[p + 9];

    float* mel  = (float*)d_out;                         // [B, MELS, T]
    float* durp = (float*)d_out + (long)B_ * MELS_ * T_; // [B, L]

    static bool attr_done = false;
    if (!attr_done) {
        cudaFuncSetAttribute(mega_kernel, cudaFuncAttributeMaxDynamicSharedMemorySize,
                             SMEM_DYN);
        attr_done = true;
    }

    mega_kernel<<<NCTA, 256, SMEM_DYN>>>(src, dur, emb, pos, W_enc, b_enc,
                                         W_dur, b_dur, W_dec, b_dec, W_gen, b_gen,
                                         mel, durp);
}

// round 11
// speedup vs baseline: 1.5275x; 1.0081x over previous
#include <cuda_runtime.h>
#include <cuda_fp16.h>
#include <cstdint>

#define B_    16
#define L_    256
#define D_    512
#define MELS_ 80
#define T_    3072
#define M_ENC (B_ * L_)   // 4096
#define NCTA  256

// Scratch (__device__ globals; no allocation allowed)
__device__ __half g_x    [M_ENC * D_];
__device__ __half g_enc  [M_ENC * D_];
__device__ __half g_dect [M_ENC * D_];
__device__ int    g_csum [B_ * L_];
__device__ float  g_melP [8 * MELS_ * M_ENC];  // per-bx gen partials [bx][n][tok]
__device__ float  g_cmel [MELS_];              // mel column for invalid frames (with bias)
__device__ __half g_wencT[D_ * D_];
__device__ __half g_wdecT[D_ * D_];
__device__ __half g_wgenT[MELS_ * D_];         // [n][k] fp16, 1KB rows

__device__ unsigned g_bar;
__device__ int fWe, fWd, fWg, fC;
__device__ int fX[32], fE[32], fRB[32], fS[16];

// ---------------------------------------------------------------------------
__device__ __forceinline__ uint32_t smem_u32(const void* p) {
    return (uint32_t)__cvta_generic_to_shared(p);
}
__device__ __forceinline__ void cpa16(uint32_t dst, const void* src, int srcsize) {
    asm volatile("cp.async.cg.shared.global [%0], [%1], 16, %2;"
                 :: "r"(dst), "l"(src), "r"(srcsize));
}
__device__ __forceinline__ uint32_t sw(uint32_t o) { return o ^ ((o >> 3) & 0x70); }

__device__ __forceinline__ void ldm4(uint32_t* r, uint32_t addr) {
    asm volatile("ldmatrix.sync.aligned.m8n8.x4.shared.b16 {%0,%1,%2,%3}, [%4];"
                 : "=r"(r[0]), "=r"(r[1]), "=r"(r[2]), "=r"(r[3]) : "r"(addr));
}
__device__ __forceinline__ void ldm2(uint32_t* r, uint32_t addr) {
    asm volatile("ldmatrix.sync.aligned.m8n8.x2.shared.b16 {%0,%1}, [%2];"
                 : "=r"(r[0]), "=r"(r[1]) : "r"(addr));
}
__device__ __forceinline__ void mma_f16(float* d, const uint32_t* a, const uint32_t* b) {
    asm volatile(
        "mma.sync.aligned.m16n8k16.row.col.f32.f16.f16.f32 "
        "{%0,%1,%2,%3},{%4,%5,%6,%7},{%8,%9},{%0,%1,%2,%3};"
        : "+f"(d[0]), "+f"(d[1]), "+f"(d[2]), "+f"(d[3])
        : "r"(a[0]), "r"(a[1]), "r"(a[2]), "r"(a[3]), "r"(b[0]), "r"(b[1]));
}

// release-signal / acquire-wait on global int flags
__device__ __forceinline__ void signal(int* f) {
    __threadfence();
    __syncthreads();
    if (threadIdx.x == 0) atomicAdd(f, 1);
}
__device__ __forceinline__ void waitf(int* f, int tgt) {
    if (threadIdx.x == 0) {
        while (*(volatile int*)f < tgt) __nanosleep(32);
        __threadfence();
    }
    __syncthreads();
}

// ---------------------------------------------------------------------------
// prep helpers
// ---------------------------------------------------------------------------
// 32x32 transpose tile of a 512x512 fp32 weight -> fp16 [N][K]
__device__ void t_unit(const float* __restrict__ srcw, __half* __restrict__ dst,
                       int id, float* sbuf)
{
    const int tid = threadIdx.x;
    const int c0 = (id & 15) * 32, r0 = (id >> 4) * 32;
    const int tx = tid & 31, ty = tid >> 5;
    float (*tile)[33] = (float(*)[33])sbuf;
#pragma unroll
    for (int i = 0; i < 4; i++)
        tile[ty + i * 8][tx] = srcw[(r0 + ty + i * 8) * D_ + c0 + tx];
    __syncthreads();
#pragma unroll
    for (int i = 0; i < 4; i++)
        dst[(long)(c0 + ty + i * 8) * D_ + r0 + tx] =
            __float2half_rn(tile[tx][ty + i * 8]);
}

// ---------------------------------------------------------------------------
// enc GEMM tile 128m x 64n: out = fp16(relu(A @ Bt^T + bias))
// ---------------------------------------------------------------------------
#define A_T 16384
#define B_T 8192
#define STG (A_T + B_T)                 // 24576
#define SMEM_DYN (2 * STG + 1024)       // 50176

__device__ void dev_hgemm(const __half* __restrict__ A, const __half* __restrict__ Bt,
                          const float* __restrict__ bias, __half* __restrict__ out,
                          int bx, int by, char* dsm)
{
    const int tid  = threadIdx.x;
    const int warp = tid >> 5, lane = tid & 31;
    const int m0   = by * 128, n0 = bx * 64;

    const uint32_t base = (smem_u32(dsm) + 1023) & ~1023u;
    const uint32_t Aoff[2] = { base, base + STG };
    const uint32_t Boff[2] = { base + A_T, base + STG + A_T };

    const int r0  = tid >> 3;
    const int seg = (tid & 7) * 16;
    const char* ap[4];
    const char* bp[2];
    uint32_t dsta[4], dstb[2];
#pragma unroll
    for (int i = 0; i < 4; i++) {
        const int r = r0 + i * 32;
        ap[i]   = (const char*)A + (long)(m0 + r) * D_ * 2;
        dsta[i] = sw((uint32_t)(r * 128 + seg));
    }
#pragma unroll
    for (int i = 0; i < 2; i++) {
        const int r = r0 + i * 32;
        bp[i]   = (const char*)Bt + (long)(n0 + r) * D_ * 2;
        dstb[i] = sw((uint32_t)(r * 128 + seg));
    }

#define HISSUE(c, s) do {                                                     \
        const int kb = (c) * 128;                                             \
        _Pragma("unroll")                                                     \
        for (int i = 0; i < 4; i++) cpa16(Aoff[s] + dsta[i], ap[i] + kb + seg, 16); \
        _Pragma("unroll")                                                     \
        for (int i = 0; i < 2; i++) cpa16(Boff[s] + dstb[i], bp[i] + kb + seg, 16); \
        asm volatile("cp.async.commit_group;");                               \
    } while (0)

    const int mbase = (warp & 1) * 64;
    const int nbase = (warp >> 1) * 16;
    const int li  = lane & 7, grp = lane >> 3;
    const int ar  = (grp & 1) * 8 + li,  ak = (grp >> 1) * 16;
    const int br  = (grp >> 1) * 8 + li, bk = (grp & 1) * 16;
    const int g = lane >> 2, t = lane & 3;

    float acc[4][2][4] = {};

    HISSUE(0, 0);
#pragma unroll 1
    for (int c = 0; c < 8; c++) {
        if (c < 7) {
            HISSUE(c + 1, (c + 1) & 1);
            asm volatile("cp.async.wait_group 1;");
        } else {
            asm volatile("cp.async.wait_group 0;");
        }
        __syncthreads();
        const uint32_t Ab = Aoff[c & 1], Bb = Boff[c & 1];
#pragma unroll
        for (int kk = 0; kk < 4; kk++) {
            const int kb2 = kk * 32;
            uint32_t a[4][4], b[2][2];
#pragma unroll
            for (int mf = 0; mf < 4; mf++) {
                uint32_t o = (uint32_t)((mbase + mf * 16 + ar) * 128 + kb2 + ak);
                ldm4(a[mf], Ab + sw(o));
            }
            {
                uint32_t o = (uint32_t)((nbase + br) * 128 + kb2 + bk);
                uint32_t r[4]; ldm4(r, Bb + sw(o));
                b[0][0] = r[0]; b[0][1] = r[1];
                b[1][0] = r[2]; b[1][1] = r[3];
            }
#pragma unroll
            for (int mf = 0; mf < 4; mf++)
#pragma unroll
                for (int nf = 0; nf < 2; nf++)
                    mma_f16(acc[mf][nf], a[mf], b[nf]);
        }
        __syncthreads();
    }

#pragma unroll
    for (int mf = 0; mf < 4; mf++) {
        const long r0g = m0 + mbase + mf * 16 + g;
#pragma unroll
        for (int nf = 0; nf < 2; nf++) {
            const int c = n0 + nbase + nf * 8 + t * 2;
            const float b0 = bias[c], b1 = bias[c + 1];
            float v0 = acc[mf][nf][0] + b0, v1 = acc[mf][nf][1] + b1;
            float v2 = acc[mf][nf][2] + b0, v3 = acc[mf][nf][3] + b1;
            __half2 h0 = __floats2half2_rn(v0 > 0.f ? v0 : 0.f, v1 > 0.f ? v1 : 0.f);
            __half2 h1 = __floats2half2_rn(v2 > 0.f ? v2 : 0.f, v3 > 0.f ? v3 : 0.f);
            *(__half2*)(out + r0g * D_ + c)       = h0;
            *(__half2*)(out + (r0g + 8) * D_ + c) = h1;
        }
    }
#undef HISSUE
}

// ---------------------------------------------------------------------------
// dec GEMM tile + fused gen partial:
//   dec tile 128x64 (relu, fp16 -> g_dect + smem stage), then
//   melP[bx][n][tok] = stage(128x64) @ wgenT[:, bx*64 .. +64]^T   (fp32, no bias)
// ---------------------------------------------------------------------------
__device__ void dev_decgen(const float* __restrict__ bias, int bx, int by, char* dsm)
{
    const int tid  = threadIdx.x;
    const int warp = tid >> 5, lane = tid & 31;
    const int m0   = by * 128, n0 = bx * 64;

    char* p_al = (char*)(((uintptr_t)dsm + 1023) & ~(uintptr_t)1023);
    const uint32_t base = smem_u32(p_al);
    const uint32_t Aoff[2] = { base, base + STG };
    const uint32_t Boff[2] = { base + A_T, base + STG + A_T };

    const int r0  = tid >> 3;
    const int seg = (tid & 7) * 16;
    const char* ap[4];
    const char* bp[2];
    uint32_t dsta[4], dstb[2];
#pragma unroll
    for (int i = 0; i < 4; i++) {
        const int r = r0 + i * 32;
        ap[i]   = (const char*)g_enc + (long)(m0 + r) * D_ * 2;
        dsta[i] = sw((uint32_t)(r * 128 + seg));
    }
#pragma unroll
    for (int i = 0; i < 2; i++) {
        const int r = r0 + i * 32;
        bp[i]   = (const char*)g_wdecT + (long)(n0 + r) * D_ * 2;
        dstb[i] = sw((uint32_t)(r * 128 + seg));
    }

#define DISSUE(c, s) do {                                                     \
        const int kb = (c) * 128;                                             \
        _Pragma("unroll")                                                     \
        for (int i = 0; i < 4; i++) cpa16(Aoff[s] + dsta[i], ap[i] + kb + seg, 16); \
        _Pragma("unroll")                                                     \
        for (int i = 0; i < 2; i++) cpa16(Boff[s] + dstb[i], bp[i] + kb + seg, 16); \
        asm volatile("cp.async.commit_group;");                               \
    } while (0)

    const int mbase = (warp & 1) * 64;
    const int nbase = (warp >> 1) * 16;
    const int li  = lane & 7, grp = lane >> 3;
    const int ar  = (grp & 1) * 8 + li,  ak = (grp >> 1) * 16;
    const int br  = (grp >> 1) * 8 + li, bk = (grp & 1) * 16;
    const int g = lane >> 2, t = lane & 3;

    float acc[4][2][4] = {};

    DISSUE(0, 0);
#pragma unroll 1
    for (int c = 0; c < 8; c++) {
        if (c < 7) {
            DISSUE(c + 1, (c + 1) & 1);
            asm volatile("cp.async.wait_group 1;");
        } else {
            asm volatile("cp.async.wait_group 0;");
        }
        __syncthreads();
        const uint32_t Ab = Aoff[c & 1], Bb = Boff[c & 1];
#pragma unroll
        for (int kk = 0; kk < 4; kk++) {
            const int kb2 = kk * 32;
            uint32_t a[4][4], b[2][2];
#pragma unroll
            for (int mf = 0; mf < 4; mf++) {
                uint32_t o = (uint32_t)((mbase + mf * 16 + ar) * 128 + kb2 + ak);
                ldm4(a[mf], Ab + sw(o));
            }
            {
                uint32_t o = (uint32_t)((nbase + br) * 128 + kb2 + bk);
                uint32_t r[4]; ldm4(r, Bb + sw(o));
                b[0][0] = r[0]; b[0][1] = r[1];
                b[1][0] = r[2]; b[1][1] = r[3];
            }
#pragma unroll
            for (int mf = 0; mf < 4; mf++)
#pragma unroll
                for (int nf = 0; nf < 2; nf++)
                    mma_f16(acc[mf][nf], a[mf], b[nf]);
        }
        __syncthreads();
    }
#undef DISSUE

    // ---- fused gen tail ----
    // issue W_gen slice loads first (overlaps epilogue): 80 rows x 128B
    const uint32_t Bg = base + A_T;   // 16K..26K: dead buffer space
#pragma unroll
    for (int i = 0; i < 3; i++) {
        const int r = r0 + i * 32;
        if (r < MELS_)
            cpa16(Bg + sw((uint32_t)(r * 128 + seg)),
                  (const char*)g_wgenT + (long)r * 1024 + bx * 128 + seg, 16);
    }
    asm volatile("cp.async.commit_group;");

    // epilogue: bias + relu + fp16 -> g_dect and smem stage (base..16K)
#pragma unroll
    for (int mf = 0; mf < 4; mf++) {
        const int rl = mbase + mf * 16 + g;
        const long r0g = m0 + rl;
#pragma unroll
        for (int nf = 0; nf < 2; nf++) {
            const int cl = nbase + nf * 8 + t * 2;
            const int c = n0 + cl;
            const float b0 = bias[c], b1 = bias[c + 1];
            float v0 = acc[mf][nf][0] + b0, v1 = acc[mf][nf][1] + b1;
            float v2 = acc[mf][nf][2] + b0, v3 = acc[mf][nf][3] + b1;
            __half2 h0 = __floats2half2_rn(v0 > 0.f ? v0 : 0.f, v1 > 0.f ? v1 : 0.f);
            __half2 h1 = __floats2half2_rn(v2 > 0.f ? v2 : 0.f, v3 > 0.f ? v3 : 0.f);
            *(__half2*)(g_dect + r0g * D_ + c)       = h0;
            *(__half2*)(g_dect + (r0g + 8) * D_ + c) = h1;
            *(__half2*)(p_al + sw((uint32_t)(rl * 128 + cl * 2)))       = h0;
            *(__half2*)(p_al + sw((uint32_t)((rl + 8) * 128 + cl * 2))) = h1;
        }
    }
    asm volatile("cp.async.wait_group 0;");
    __syncthreads();

    // small gemm: 128 tok x 80 n x 64 k; 8 warps = 4m x 2n
    const int mb2 = (warp & 3) * 32, nb2 = (warp >> 2) * 40;
    float acc2[2][5][4] = {};
#pragma unroll
    for (int kk = 0; kk < 4; kk++) {
        const int kb2 = kk * 32;
        uint32_t a2[2][4], b2[5][2];
#pragma unroll
        for (int mf = 0; mf < 2; mf++)
            ldm4(a2[mf], base + sw((uint32_t)((mb2 + mf * 16 + ar) * 128 + kb2 + ak)));
#pragma unroll
        for (int nfp = 0; nfp < 2; nfp++) {
            uint32_t r[4];
            ldm4(r, Bg + sw((uint32_t)((nb2 + nfp * 16 + br) * 128 + kb2 + bk)));
            b2[nfp * 2][0] = r[0]; b2[nfp * 2][1] = r[1];
            b2[nfp * 2 + 1][0] = r[2]; b2[nfp * 2 + 1][1] = r[3];
        }
        ldm2(b2[4], Bg + sw((uint32_t)((nb2 + 32 + li) * 128 + kb2 + (grp & 1) * 16)));
#pragma unroll
        for (int mf = 0; mf < 2; mf++)
#pragma unroll
            for (int nf = 0; nf < 5; nf++)
                mma_f16(acc2[mf][nf], a2[mf], b2[nf]);
    }

    // write fp32 partials: g_melP[bx][n][tok]
#pragma unroll
    for (int mf = 0; mf < 2; mf++) {
        const int tok = m0 + mb2 + mf * 16 + g;
#pragma unroll
        for (int nf = 0; nf < 5; nf++) {
            const int n = nb2 + nf * 8 + t * 2;
            float* p = g_melP + ((long)bx * MELS_ + n) * M_ENC + tok;
            p[0]           = acc2[mf][nf][0];
            p[M_ENC]       = acc2[mf][nf][1];
            p[8]           = acc2[mf][nf][2];
            p[M_ENC + 8]   = acc2[mf][nf][3];
        }
    }
}

// ---------------------------------------------------------------------------
// mega kernel, fully dataflow
// ---------------------------------------------------------------------------
__global__ void __launch_bounds__(256, 2) mega_kernel(
    const int* __restrict__ src, const int* __restrict__ dur,
    const float* __restrict__ emb, const float* __restrict__ pos,
    const float* __restrict__ W_enc, const float* __restrict__ b_enc,
    const float* __restrict__ W_dur, const float* __restrict__ b_dur,
    const float* __restrict__ W_dec, const float* __restrict__ b_dec,
    const float* __restrict__ W_gen, const float* __restrict__ b_gen,
    float* __restrict__ mel, float* __restrict__ durp)
{
    extern __shared__ char dsm[];
    __shared__ float sbuf[32 * 33];
    __shared__ float bsh[MELS_];
    const int cta = blockIdx.x;
    const int tid = threadIdx.x;

    // ---------------- prep stream ----------------
    // wenc transpose (unit = cta)
    t_unit(W_enc, g_wencT, cta, sbuf);
    signal(&fWe);

    // prep_x: 8 units covering rows 16*cta .. +15
#pragma unroll 1
    for (int i = 0; i < 8; i++) {
        const long idx = ((long)cta * 8 + i) * 256 + tid;    // float4 index
        const int  m   = (int)(idx >> 7);
        const int  d4  = (int)(idx & 127) * 4;
        float4 e = *(const float4*)(emb + (long)src[m] * D_ + d4);
        float4 p = *(const float4*)(pos + (long)(m & (L_ - 1)) * D_ + d4);
        __half2 h0 = __floats2half2_rn(e.x + p.x, e.y + p.y);
        __half2 h1 = __floats2half2_rn(e.z + p.z, e.w + p.w);
        uint2 u = make_uint2(*(uint32_t*)&h0, *(uint32_t*)&h1);
        *(uint2*)(g_x + idx * 4) = u;
    }
    signal(&fX[cta >> 3]);

    // wdec transpose (unit = cta)
    t_unit(W_dec, g_wdecT, cta, sbuf);
    signal(&fWd);

    // extras
    if (cta < 48) {
        // W_gen [D][MELS] -> g_wgenT [MELS][D], 32x32 tiles (3 x 16)
        const int c0 = (cta % 3) * 32, r0 = (cta / 3) * 32;
        const int tx = tid & 31, ty = tid >> 5;
        float (*tile)[33] = (float(*)[33])sbuf;
#pragma unroll
        for (int i = 0; i < 4; i++) {
            int r = r0 + ty + i * 8, c = c0 + tx;
            if (c < MELS_) tile[ty + i * 8][tx] = W_gen[r * MELS_ + c];
        }
        __syncthreads();
#pragma unroll
        for (int i = 0; i < 4; i++) {
            int c = c0 + ty + i * 8, r = r0 + tx;
            if (c < MELS_)
                g_wgenT[(long)c * D_ + r] = __float2half_rn(tile[tx][ty + i * 8]);
        }
        signal(&fWg);
    } else if (cta < 64) {
        // per-batch duration scan
        const int b = cta - 48;
        int* csum = (int*)sbuf;
        csum[tid] = dur[b * L_ + tid];
        __syncthreads();
        for (int off = 1; off < L_; off <<= 1) {
            int x = (tid >= off) ? csum[tid - off] : 0;
            __syncthreads();
            csum[tid] += x;
            __syncthreads();
        }
        g_csum[b * L_ + tid] = csum[tid];
        signal(&fS[b]);
    } else if (cta == 64) {
        // cmel (full value incl. bias)
        float* rd = sbuf;
        for (int k = tid; k < D_; k += 256) {
            float v = b_dec[k]; rd[k] = v > 0.f ? v : 0.f;
        }
        __syncthreads();
        if (tid < MELS_) {
            float s = b_gen[tid];
            for (int k = 0; k < D_; k++) s += rd[k] * W_gen[k * MELS_ + tid];
            g_cmel[tid] = s;
        }
        signal(&fC);
    }

    // ---------------- enc ----------------
    waitf(&fWe, 256);
    waitf(&fX[cta >> 3], 8);
    dev_hgemm(g_x, g_wencT, b_enc, g_enc, cta & 7, cta >> 3, dsm);
    signal(&fE[cta >> 3]);

    // ---------------- dec + fused gen ----------------
    waitf(&fE[cta >> 3], 8);
    waitf(&fWd, 256);
    waitf(&fWg, 48);
    dev_decgen(b_dec, cta & 7, cta >> 3, dsm);
    signal(&fRB[cta >> 3]);

    // ---------------- dur / expand ----------------
    if (cta < 64) {
        // duration head: rows 64*cta .. +63 (needs enc row-block cta>>1)
        waitf(&fE[cta >> 1], 8);
        const int warp = tid >> 5, lane = tid & 31;
#pragma unroll 1
        for (int i = 0; i < 8; i++) {
            const int m = cta * 64 + warp * 8 + i;
            float s = 0.f;
            for (int k = lane; k < D_; k += 32)
                s += __half2float(g_enc[(long)m * D_ + k]) * W_dur[k];
#pragma unroll
            for (int o = 16; o; o >>= 1) s += __shfl_xor_sync(0xffffffffu, s, o);
            if (lane == 0) durp[m] = s + b_dur[0];
        }
    } else {
        // expand: one 256-frame unit per CTA
        const int u  = cta - 64;
        const int b  = u & (B_ - 1);
        const int t0 = (u >> 4) * 256;
        waitf(&fRB[2 * b], 8);
        waitf(&fRB[2 * b + 1], 8);
        waitf(&fS[b], 1);
        waitf(&fC, 1);

        int* csum = (int*)sbuf;
        csum[tid] = g_csum[b * L_ + tid];
        if (tid < MELS_) bsh[tid] = b_gen[tid];
        __syncthreads();

        const int t = t0 + tid;
        int lo = 0, hi = L_;
        while (lo < hi) {
            int mid = (lo + hi) >> 1;
            if (csum[mid] > t) hi = mid; else lo = mid + 1;
        }
        float* out = mel + (long)b * MELS_ * T_ + t;
        if (lo < L_) {
            const int tok = b * L_ + lo;
            const float* q = g_melP + tok;
#pragma unroll 4
            for (int n = 0; n < MELS_; n++) {
                float s = bsh[n];
#pragma unroll
                for (int x = 0; x < 8; x++)
                    s += __ldg(q + ((long)x * MELS_ + n) * M_ENC);
                out[(long)n * T_] = s;
            }
        } else {
#pragma unroll 4
            for (int n = 0; n < MELS_; n++)
                out[(long)n * T_] = g_cmel[n];
        }
    }

    // ---------------- final reset (last arrival) ----------------
    __threadfence();
    __syncthreads();
    if (tid == 0) {
        unsigned v = atomicAdd(&g_bar, 1u);
        if (v == (unsigned)NCTA - 1u) {
            fWe = 0; fWd = 0; fWg = 0; fC = 0;
            for (int i = 0; i < 32; i++) { fX[i] = 0; fE[i] = 0; fRB[i] = 0; }
            for (int i = 0; i < 16; i++) fS[i] = 0;
            atomicExch(&g_bar, 0u);
        }
    }
}

// ---------------------------------------------------------------------------
extern "C" void kernel_launch(void* const* d_in, const int* in_sizes, int n_in,
                              void* d_out, int out_size)
{
    const int* src = (const int*)d_in[0];
    const int* dur = (const int*)d_in[1];
    int p = 2;
    if (p < n_in && in_sizes[2] <= 4) p = 3;  // skip scalar T if materialized
    const float* emb   = (const float*)d_in[p + 0];
    const float* pos   = (const float*)d_in[p + 1];
    const float* W_enc = (const float*)d_in[p + 2];
    const float* b_enc = (const float*)d_in[p + 3];
    const float* W_dur = (const float*)d_in[p + 4];
    const float* b_dur = (const float*)d_in[p + 5];
    const float* W_dec = (const float*)d_in[p + 6];
    const float* b_dec = (const float*)d_in[p + 7];
    const float* W_gen = (const float*)d_in[p + 8];
    const float* b_gen = (const float*)d_in[p + 9];

    float* mel  = (float*)d_out;                         // [B, MELS, T]
    float* durp = (float*)d_out + (long)B_ * MELS_ * T_; // [B, L]

    static bool attr_done = false;
    if (!attr_done) {
        cudaFuncSetAttribute(mega_kernel, cudaFuncAttributeMaxDynamicSharedMemorySize,
                             SMEM_DYN);
        attr_done = true;
    }

    mega_kernel<<<NCTA, 256, SMEM_DYN>>>(src, dur, emb, pos, W_enc, b_enc,
                                         W_dur, b_dur, W_dec, b_dec, W_gen, b_gen,
                                         mel, durp);
}